// round 12
// baseline (speedup 1.0000x reference)
#include <cuda_runtime.h>
#include <cuda_fp16.h>
#include <math.h>
#include <stdint.h>

#define HIDDEN 2560
#define NH 32
#define NKV 8
#define HD 80
#define BATCH 2
#define SEQ 2048
#define M_TOK (BATCH * SEQ)   // 4096

// ---------------- scratch (static device globals; no runtime alloc) ----------
__device__ __half g_qh[M_TOK * NH * HD];
__device__ __half g_kh[M_TOK * NKV * HD];
__device__ __half g_vh[M_TOK * NKV * HD];
__device__ __half g_oh[M_TOK * NH * HD];       // attn out, half, K-major
__device__ __half g_xh[M_TOK * HIDDEN];        // x rounded to half
__device__ __half g_wqh[HIDDEN * NH * HD];     // weights: transposed [N,K] half
__device__ __half g_wkh[HIDDEN * NKV * HD];
__device__ __half g_wvh[HIDDEN * NKV * HD];
__device__ __half g_woh[NH * HD * HIDDEN];

__device__ __forceinline__ void mma_f16(float* c, const unsigned* a,
                                        unsigned b0, unsigned b1) {
    asm volatile(
        "mma.sync.aligned.m16n8k16.row.col.f32.f16.f16.f32 "
        "{%0,%1,%2,%3}, {%4,%5,%6,%7}, {%8,%9}, {%0,%1,%2,%3};"
        : "+f"(c[0]), "+f"(c[1]), "+f"(c[2]), "+f"(c[3])
        : "r"(a[0]), "r"(a[1]), "r"(a[2]), "r"(a[3]),
          "r"(b0), "r"(b1));
}

__device__ __forceinline__ void ldsm_x4(unsigned& r0, unsigned& r1,
                                        unsigned& r2, unsigned& r3,
                                        uint32_t addr) {
    asm volatile("ldmatrix.sync.aligned.m8n8.x4.shared.b16 {%0,%1,%2,%3}, [%4];"
                 : "=r"(r0), "=r"(r1), "=r"(r2), "=r"(r3) : "r"(addr));
}

__device__ __forceinline__ unsigned packh2(float x, float y) {
    __half2 h = __floats2half2_rn(x, y);
    return *(unsigned*)&h;
}

__device__ __forceinline__ void cp_async16(void* smem_ptr, const void* gptr) {
    unsigned saddr = (unsigned)__cvta_generic_to_shared(smem_ptr);
    asm volatile("cp.async.cg.shared.global [%0], [%1], 16;\n"
                 :: "r"(saddr), "l"(gptr));
}
__device__ __forceinline__ void cp_commit() {
    asm volatile("cp.async.commit_group;\n");
}
__device__ __forceinline__ void cp_wait0() {
    asm volatile("cp.async.wait_group 0;\n");
}
__device__ __forceinline__ void cp_wait1() {
    asm volatile("cp.async.wait_group 1;\n");
}

// typed paired store
__device__ __forceinline__ void store2(float* p, float a, float b) {
    *(float2*)p = make_float2(a, b);
}
__device__ __forceinline__ void store2(__half* p, float a, float b) {
    *(__half2*)p = __floats2half2_rn(a, b);
}

// ---------------- prep: fp32 -> fp16 -------------------------------------------
__global__ void f2h_kernel(const float* __restrict__ in,
                           __half* __restrict__ out, int n8)
{
    int i = blockIdx.x * blockDim.x + threadIdx.x;
    if (i >= n8) return;
    const float4* ip = (const float4*)in + (size_t)i * 2;
    float4 a = ip[0], b = ip[1];
    uint4 o;
    o.x = packh2(a.x, a.y); o.y = packh2(a.z, a.w);
    o.z = packh2(b.x, b.y); o.w = packh2(b.z, b.w);
    *((uint4*)out + i) = o;
}

// ---------------- prep: 4 weight transposes in one launch ----------------------
// segment s: in[K,N] fp32 -> out[N,K] fp16; flat 32x32 tile id per segment
__global__ void f2h_transpose4_kernel(
    const float* __restrict__ i0, __half* __restrict__ o0, int k0d, int n0d, int c0,
    const float* __restrict__ i1, __half* __restrict__ o1, int k1d, int n1d, int c1,
    const float* __restrict__ i2, __half* __restrict__ o2, int k2d, int n2d, int c2,
    const float* __restrict__ i3, __half* __restrict__ o3, int k3d, int n3d)
{
    __shared__ float t[32][33];
    int bidx = blockIdx.x;
    const float* in; __half* out; int Kdim, Ndim, lid;
    if (bidx < c0)      { in = i0; out = o0; Kdim = k0d; Ndim = n0d; lid = bidx; }
    else if (bidx < c1) { in = i1; out = o1; Kdim = k1d; Ndim = n1d; lid = bidx - c0; }
    else if (bidx < c2) { in = i2; out = o2; Kdim = k2d; Ndim = n2d; lid = bidx - c1; }
    else                { in = i3; out = o3; Kdim = k3d; Ndim = n3d; lid = bidx - c2; }

    int ntx = Ndim / 32;
    int n0 = (lid % ntx) * 32;
    int k0 = (lid / ntx) * 32;
    #pragma unroll
    for (int j = 0; j < 4; j++)
        t[threadIdx.y + j * 8][threadIdx.x] =
            in[(size_t)(k0 + threadIdx.y + j * 8) * Ndim + n0 + threadIdx.x];
    __syncthreads();
    #pragma unroll
    for (int j = 0; j < 4; j++)
        out[(size_t)(n0 + threadIdx.y + j * 8) * Kdim + k0 + threadIdx.x] =
            __float2half_rn(t[threadIdx.x][threadIdx.y + j * 8]);
}

// ---------------- pipelined FP16 GEMM (3-stage, ldmatrix), 3 segments ----------
#define HSTR 40
#define TILEH (128 * HSTR)
#define STGH  (2 * TILEH)
#define GEMM_SMEM (3 * STGH * 2)        // 61440 bytes

template <typename OutT>
__global__ __launch_bounds__(256) void h16_gemm3_kernel(
    const __half* __restrict__ A,
    const __half* __restrict__ B0, OutT* __restrict__ C0, int N0, int xs0,
    const __half* __restrict__ B1, OutT* __restrict__ C1, int N1, int xs1,
    const __half* __restrict__ B2, OutT* __restrict__ C2, int N2,
    int M, int K)
{
    extern __shared__ __half smh[];
    const uint32_t sbase = (uint32_t)__cvta_generic_to_shared(smh);

    const int bx = blockIdx.x;
    const __half* B; OutT* C; int N; int bxl;
    if (bx < xs0)      { B = B0; C = C0; N = N0; bxl = bx; }
    else if (bx < xs1) { B = B1; C = C1; N = N1; bxl = bx - xs0; }
    else               { B = B2; C = C2; N = N2; bxl = bx - xs1; }

    const int tid  = threadIdx.x;
    const int lane = tid & 31;
    const int warp = tid >> 5;
    const int wm   = (warp & 3) * 32;
    const int wn   = (warp >> 2) * 64;
    const int bm   = blockIdx.y * 128;
    const int bn   = bxl * 128;
    const int lq   = lane >> 2;
    const int lr   = lane & 3;

    const int arow_l = (lane & 7) + ((lane >> 3) & 1) * 8;
    const int awrd_l = (lane >> 4) * 4;
    const int brow_l = (lane & 7) + (lane >> 4) * 8;
    const int bwrd_l = ((lane >> 3) & 1) * 4;

    const int cr = tid >> 2;
    const int cc = tid & 3;

    float acc[2][8][4];
    #pragma unroll
    for (int i = 0; i < 2; i++)
        #pragma unroll
        for (int j = 0; j < 8; j++)
            #pragma unroll
            for (int r = 0; r < 4; r++) acc[i][j][r] = 0.f;

    const int T = K / 32;

    auto issue = [&](int t) {
        __half* sA = smh + (t % 3) * STGH;
        __half* sB = sA + TILEH;
        const int k0 = t * 32;
        #pragma unroll
        for (int i = 0; i < 2; i++) {
            int r = cr + i * 64;
            cp_async16(sA + r * HSTR + cc * 8, A + (size_t)(bm + r) * K + k0 + cc * 8);
            cp_async16(sB + r * HSTR + cc * 8, B + (size_t)(bn + r) * K + k0 + cc * 8);
        }
    };

    issue(0); cp_commit();
    issue(1); cp_commit();

    for (int t = 0; t < T; t++) {
        cp_wait1();
        __syncthreads();

        if (t + 2 < T) issue(t + 2);
        cp_commit();

        const uint32_t stA = sbase + (uint32_t)((t % 3) * STGH) * 2;
        const uint32_t stB = stA + TILEH * 2;
        #pragma unroll
        for (int ks = 0; ks < 2; ks++) {
            const int c8 = ks * 8;
            unsigned af[2][4];
            #pragma unroll
            for (int mi = 0; mi < 2; mi++)
                ldsm_x4(af[mi][0], af[mi][1], af[mi][2], af[mi][3],
                        stA + (uint32_t)(wm + mi * 16 + arow_l) * 80
                            + (uint32_t)(c8 + awrd_l) * 4);
            unsigned bf[8][2];
            #pragma unroll
            for (int nb = 0; nb < 8; nb += 2)
                ldsm_x4(bf[nb][0], bf[nb][1], bf[nb + 1][0], bf[nb + 1][1],
                        stB + (uint32_t)(wn + nb * 8 + brow_l) * 80
                            + (uint32_t)(c8 + bwrd_l) * 4);
            #pragma unroll
            for (int mi = 0; mi < 2; mi++)
                #pragma unroll
                for (int ni = 0; ni < 8; ni++)
                    mma_f16(acc[mi][ni], af[mi], bf[ni][0], bf[ni][1]);
        }
    }

    #pragma unroll
    for (int mi = 0; mi < 2; mi++) {
        int m = bm + wm + mi * 16 + lq;
        #pragma unroll
        for (int ni = 0; ni < 8; ni++) {
            int n = bn + wn + ni * 8 + lr * 2;
            store2(C + (size_t)m * N + n,       acc[mi][ni][0], acc[mi][ni][1]);
            store2(C + (size_t)(m + 8) * N + n, acc[mi][ni][2], acc[mi][ni][3]);
        }
    }
}

// ---------------- fused RoPE (half2 vectorized) ---------------------------------
__global__ void rope_fused_kernel(__half* __restrict__ qb, __half* __restrict__ kb,
                                  const float* __restrict__ cosf,
                                  const float* __restrict__ sinf,
                                  int tq, int total)
{
    int idx = blockIdx.x * blockDim.x + threadIdx.x;
    if (idx >= total) return;
    __half* t; int nheads; int li;
    if (idx < tq) { t = qb; nheads = NH;  li = idx; }
    else          { t = kb; nheads = NKV; li = idx - tq; }

    int i2  = li % 20;                  // pair-of-pairs index
    int h   = (li / 20) % nheads;
    int tok = li / (20 * nheads);
    int s   = tok % SEQ;
    int i   = i2 * 2;

    __half* p = t + (size_t)tok * nheads * HD + h * HD;
    float2 xa = __half22float2(*(__half2*)(p + i));
    float2 xb = __half22float2(*(__half2*)(p + i + 40));
    float2 c1 = *(const float2*)(cosf + s * HD + i);
    float2 s1 = *(const float2*)(sinf + s * HD + i);
    float2 c2 = *(const float2*)(cosf + s * HD + i + 40);
    float2 s2 = *(const float2*)(sinf + s * HD + i + 40);
    *(__half2*)(p + i)      = __floats2half2_rn(xa.x * c1.x - xb.x * s1.x,
                                                xa.y * c1.y - xb.y * s1.y);
    *(__half2*)(p + i + 40) = __floats2half2_rn(xb.x * c2.x + xa.x * s2.x,
                                                xb.y * c2.y + xa.y * s2.y);
}

// ---------------- FP16 flash attention: KT=64, 2 CTAs/SM -----------------------
#define QW2 44                // Q/K row stride (words, 176B; ==12 mod 32)
#define VW2 36                // Vt/Ps row stride (words, 144B; ==4 mod 32)
#define ATT_WORDS2 (128 * QW2 + 64 * QW2 + 80 * VW2 + 128 * VW2)   // 15936
#define ATT_SMEM2  (ATT_WORDS2 * 4)    // 63744 bytes

__global__ __launch_bounds__(256, 2) void attn_h16_kernel(
    const __half* __restrict__ q, const __half* __restrict__ k,
    const __half* __restrict__ v, __half* __restrict__ oh)
{
    extern __shared__ unsigned sw[];
    unsigned* Pw = sw + 128 * QW2 + 64 * QW2 + 80 * VW2;
    __half* Qh = (__half*)sw;
    __half* Kh = (__half*)(sw + 128 * QW2);
    __half* Vh = (__half*)(sw + 128 * QW2 + 64 * QW2);
    const uint32_t sbase = (uint32_t)__cvta_generic_to_shared(sw);
    const uint32_t Qb = sbase;
    const uint32_t Kb = Qb + 128 * QW2 * 4;
    const uint32_t Vb = Kb + 64 * QW2 * 4;
    const uint32_t Pb = Vb + 80 * VW2 * 4;

    const int b    = blockIdx.z;
    const int h    = blockIdx.y;
    const int qt   = gridDim.x - 1 - blockIdx.x;   // longest blocks first
    const int kvh  = h >> 2;
    const int tid  = threadIdx.x;
    const int lane = tid & 31;
    const int warp = tid >> 5;
    const int lq   = lane >> 2;
    const int lr   = lane & 3;
    const int wr   = warp * 16;
    const float scale = rsqrtf((float)HD);

    const int arow_l = (lane & 7) + ((lane >> 3) & 1) * 8;
    const int awrd_l = (lane >> 4) * 4;
    const int brow_l = (lane & 7) + (lane >> 4) * 8;
    const int bwrd_l = ((lane >> 3) & 1) * 4;

    // ---- load Q tile (128 x 80 half) via cp.async ----
    {
        const __half* qsrc = q + ((size_t)(b * SEQ + qt * 128)) * (NH * HD) + h * HD;
        #pragma unroll
        for (int i = 0; i < 5; i++) {
            int f   = tid + i * 256;
            int row = f / 10;
            int ch  = f % 10;
            cp_async16(Qh + row * (2 * QW2) + ch * 8,
                       qsrc + (size_t)row * (NH * HD) + ch * 8);
        }
        cp_commit();
    }

    float oacc[10][4];
    #pragma unroll
    for (int i = 0; i < 10; i++)
        #pragma unroll
        for (int j = 0; j < 4; j++) oacc[i][j] = 0.f;
    float m0 = -INFINITY, m1 = -INFINITY;
    float l0 = 0.f, l1 = 0.f;

    const int row0 = qt * 128 + wr + lq;
    const int row1 = row0 + 8;
    const int ktmax = 2 * qt + 1;

    for (int kt = 0; kt <= ktmax; kt++) {
        __syncthreads();   // previous iteration fully consumed K/V smem
        // ---- K via cp.async; V^T scatter (64 keys x 80 d) ----
        {
            const __half* ksrc = k + ((size_t)(b * SEQ + kt * 64)) * (NKV * HD) + kvh * HD;
            const __half* vsrc = v + ((size_t)(b * SEQ + kt * 64)) * (NKV * HD) + kvh * HD;
            #pragma unroll
            for (int i = 0; i < 3; i++) {
                int f = tid + i * 256;
                if (f < 640) {
                    int row = f / 10;
                    int ch  = f % 10;
                    cp_async16(Kh + row * (2 * QW2) + ch * 8,
                               ksrc + (size_t)row * (NKV * HD) + ch * 8);
                    uint4 vv = *(const uint4*)(vsrc + (size_t)row * (NKV * HD) + ch * 8);
                    __half hv[8];
                    *(uint4*)hv = vv;
                    #pragma unroll
                    for (int j = 0; j < 8; j++)
                        Vh[(ch * 8 + j) * (2 * VW2) + row] = hv[j];
                }
            }
            cp_commit();
            cp_wait0();
        }
        __syncthreads();

        // ---- QK^T: S[16 x 64] per warp, 5 k-steps of 16 ----
        float sc[8][4];
        #pragma unroll
        for (int ni = 0; ni < 8; ni++)
            #pragma unroll
            for (int j = 0; j < 4; j++) sc[ni][j] = 0.f;

        #pragma unroll
        for (int ks = 0; ks < 5; ks++) {
            const int c8 = ks * 8;
            unsigned af[4];
            ldsm_x4(af[0], af[1], af[2], af[3],
                    Qb + (uint32_t)(wr + arow_l) * 176 + (uint32_t)(c8 + awrd_l) * 4);
            unsigned bf[8][2];
            #pragma unroll
            for (int nb = 0; nb < 8; nb += 2)
                ldsm_x4(bf[nb][0], bf[nb][1], bf[nb + 1][0], bf[nb + 1][1],
                        Kb + (uint32_t)(nb * 8 + brow_l) * 176
                           + (uint32_t)(c8 + bwrd_l) * 4);
            #pragma unroll
            for (int ni = 0; ni < 8; ni++)
                mma_f16(sc[ni], af, bf[ni][0], bf[ni][1]);
        }

        // ---- scale + causal mask (only last two k-subtiles can clip) ----
        const bool diag = (kt >= 2 * qt);
        #pragma unroll
        for (int ni = 0; ni < 8; ni++) {
            int c = kt * 64 + ni * 8 + lr * 2;
            sc[ni][0] = (diag && c     > row0) ? -1e30f : sc[ni][0] * scale;
            sc[ni][1] = (diag && c + 1 > row0) ? -1e30f : sc[ni][1] * scale;
            sc[ni][2] = (diag && c     > row1) ? -1e30f : sc[ni][2] * scale;
            sc[ni][3] = (diag && c + 1 > row1) ? -1e30f : sc[ni][3] * scale;
        }

        // ---- online softmax ----
        float rm0 = -1e30f, rm1 = -1e30f;
        #pragma unroll
        for (int ni = 0; ni < 8; ni++) {
            rm0 = fmaxf(rm0, fmaxf(sc[ni][0], sc[ni][1]));
            rm1 = fmaxf(rm1, fmaxf(sc[ni][2], sc[ni][3]));
        }
        rm0 = fmaxf(rm0, __shfl_xor_sync(0xffffffffu, rm0, 1));
        rm0 = fmaxf(rm0, __shfl_xor_sync(0xffffffffu, rm0, 2));
        rm1 = fmaxf(rm1, __shfl_xor_sync(0xffffffffu, rm1, 1));
        rm1 = fmaxf(rm1, __shfl_xor_sync(0xffffffffu, rm1, 2));

        float m0n = fmaxf(m0, rm0);
        float m1n = fmaxf(m1, rm1);
        float a0  = __expf(m0 - m0n);
        float a1  = __expf(m1 - m1n);
        m0 = m0n; m1 = m1n;

        float rs0 = 0.f, rs1 = 0.f;
        #pragma unroll
        for (int ni = 0; ni < 8; ni++) {
            float p0 = __expf(sc[ni][0] - m0n);
            float p1 = __expf(sc[ni][1] - m0n);
            float p2 = __expf(sc[ni][2] - m1n);
            float p3 = __expf(sc[ni][3] - m1n);
            rs0 += p0 + p1;
            rs1 += p2 + p3;
            Pw[(wr + lq    ) * VW2 + ni * 4 + lr] = packh2(p0, p1);
            Pw[(wr + lq + 8) * VW2 + ni * 4 + lr] = packh2(p2, p3);
        }
        rs0 += __shfl_xor_sync(0xffffffffu, rs0, 1);
        rs0 += __shfl_xor_sync(0xffffffffu, rs0, 2);
        rs1 += __shfl_xor_sync(0xffffffffu, rs1, 1);
        rs1 += __shfl_xor_sync(0xffffffffu, rs1, 2);
        l0 = l0 * a0 + rs0;
        l1 = l1 * a1 + rs1;

        #pragma unroll
        for (int ni = 0; ni < 10; ni++) {
            oacc[ni][0] *= a0; oacc[ni][1] *= a0;
            oacc[ni][2] *= a1; oacc[ni][3] *= a1;
        }

        __syncwarp();   // Ps rows are warp-private

        // ---- PV: O[16 x 80] += P[16 x 64] @ V[64 x 80], 4 k-steps ----
        #pragma unroll
        for (int ks = 0; ks < 4; ks++) {
            const int c8 = ks * 8;
            unsigned af[4];
            ldsm_x4(af[0], af[1], af[2], af[3],
                    Pb + (uint32_t)(wr + arow_l) * 144 + (uint32_t)(c8 + awrd_l) * 4);
            unsigned bf[10][2];
            #pragma unroll
            for (int nb = 0; nb < 10; nb += 2)
                ldsm_x4(bf[nb][0], bf[nb][1], bf[nb + 1][0], bf[nb + 1][1],
                        Vb + (uint32_t)(nb * 8 + brow_l) * 144
                           + (uint32_t)(c8 + bwrd_l) * 4);
            #pragma unroll
            for (int ni = 0; ni < 10; ni++)
                mma_f16(oacc[ni], af, bf[ni][0], bf[ni][1]);
        }
    }

    // ---- epilogue: fp16 output feeds the fp16 Wo GEMM ----
    const float inv0 = 1.0f / l0;
    const float inv1 = 1.0f / l1;
    #pragma unroll
    for (int ni = 0; ni < 10; ni++) {
        int c = ni * 8 + lr * 2;
        __half2* p0 = (__half2*)(oh + (size_t)(b * SEQ + row0) * (NH * HD) + h * HD + c);
        __half2* p1 = (__half2*)(oh + (size_t)(b * SEQ + row1) * (NH * HD) + h * HD + c);
        *p0 = __floats2half2_rn(oacc[ni][0] * inv0, oacc[ni][1] * inv0);
        *p1 = __floats2half2_rn(oacc[ni][2] * inv1, oacc[ni][3] * inv1);
    }
}

// ---------------- launch --------------------------------------------------------
extern "C" void kernel_launch(void* const* d_in, const int* in_sizes, int n_in,
                              void* d_out, int out_size)
{
    const float* x    = (const float*)d_in[0];
    const float* cosf = (const float*)d_in[1];
    const float* sinf = (const float*)d_in[2];
    const float* Wq   = (const float*)d_in[3];
    const float* Wk   = (const float*)d_in[4];
    const float* Wv   = (const float*)d_in[5];
    const float* Wo   = (const float*)d_in[6];
    float* out = (float*)d_out;

    __half *qhb, *khb, *vhb, *ohb, *xh, *wqh, *wkh, *wvh, *woh;
    cudaGetSymbolAddress((void**)&qhb, g_qh);
    cudaGetSymbolAddress((void**)&khb, g_kh);
    cudaGetSymbolAddress((void**)&vhb, g_vh);
    cudaGetSymbolAddress((void**)&ohb, g_oh);
    cudaGetSymbolAddress((void**)&xh, g_xh);
    cudaGetSymbolAddress((void**)&wqh, g_wqh);
    cudaGetSymbolAddress((void**)&wkh, g_wkh);
    cudaGetSymbolAddress((void**)&wvh, g_wvh);
    cudaGetSymbolAddress((void**)&woh, g_woh);

    // prep: x -> half; 4 weight transposes in one launch
    {
        int n8 = M_TOK * HIDDEN / 8;
        f2h_kernel<<<(n8 + 255) / 256, 256>>>(x, xh, n8);
        // tile counts: Wq 80x80=6400, Wk 20x80=1600, Wv 1600, Wo 80x80=6400
        int c0 = 6400, c1 = c0 + 1600, c2 = c1 + 1600, ctot = c2 + 6400;
        dim3 blk(32, 8);
        f2h_transpose4_kernel<<<ctot, blk>>>(
            Wq, wqh, HIDDEN, NH * HD, c0,
            Wk, wkh, HIDDEN, NKV * HD, c1,
            Wv, wvh, HIDDEN, NKV * HD, c2,
            Wo, woh, NH * HD, HIDDEN);
    }

    cudaFuncSetAttribute(h16_gemm3_kernel<__half>,
                         cudaFuncAttributeMaxDynamicSharedMemorySize, GEMM_SMEM);
    cudaFuncSetAttribute(h16_gemm3_kernel<float>,
                         cudaFuncAttributeMaxDynamicSharedMemorySize, GEMM_SMEM);

    // fused Q/K/V projections (fp16 mma, half outputs)
    {
        dim3 g(30, M_TOK / 128);
        h16_gemm3_kernel<__half><<<g, 256, GEMM_SMEM>>>(
            xh,
            wqh, qhb, NH * HD, 20,
            wkh, khb, NKV * HD, 25,
            wvh, vhb, NKV * HD,
            M_TOK, HIDDEN);
    }

    // fused RoPE (half2)
    {
        int tq = M_TOK * NH * 20;
        int tk = M_TOK * NKV * 20;
        int tot = tq + tk;
        rope_fused_kernel<<<(tot + 255) / 256, 256>>>(qhb, khb, cosf, sinf, tq, tot);
    }

    // attention (fp16 mma flash, KT=64, 2 CTAs/SM)
    {
        cudaFuncSetAttribute(attn_h16_kernel,
                             cudaFuncAttributeMaxDynamicSharedMemorySize, ATT_SMEM2);
        dim3 ga(SEQ / 128, NH, BATCH);
        attn_h16_kernel<<<ga, 256, ATT_SMEM2>>>(qhb, khb, vhb, ohb);
    }

    // output projection (fp16 mma, fp32 output)
    {
        dim3 go(HIDDEN / 128, M_TOK / 128);
        h16_gemm3_kernel<float><<<go, 256, GEMM_SMEM>>>(
            ohb,
            woh, out, HIDDEN, 20,
            woh, out, HIDDEN, 20,
            woh, out, HIDDEN,
            M_TOK, HIDDEN);
    }
}

// round 13
// speedup vs baseline: 1.7160x; 1.7160x over previous
#include <cuda_runtime.h>
#include <cuda_fp16.h>
#include <math.h>
#include <stdint.h>

#define HIDDEN 2560
#define NH 32
#define NKV 8
#define HD 80
#define BATCH 2
#define SEQ 2048
#define M_TOK (BATCH * SEQ)   // 4096

// ---------------- scratch (static device globals; no runtime alloc) ----------
__device__ __half g_qh[M_TOK * NH * HD];
__device__ __half g_kh[M_TOK * NKV * HD];
__device__ __half g_vh[M_TOK * NKV * HD];
__device__ __half g_oh[M_TOK * NH * HD];       // attn out, half, K-major
__device__ __half g_xh[M_TOK * HIDDEN];        // x rounded to half
__device__ __half g_wqh[HIDDEN * NH * HD];     // weights: transposed [N,K] half
__device__ __half g_wkh[HIDDEN * NKV * HD];
__device__ __half g_wvh[HIDDEN * NKV * HD];
__device__ __half g_woh[NH * HD * HIDDEN];

__device__ __forceinline__ void mma_f16(float* c, const unsigned* a,
                                        unsigned b0, unsigned b1) {
    asm volatile(
        "mma.sync.aligned.m16n8k16.row.col.f32.f16.f16.f32 "
        "{%0,%1,%2,%3}, {%4,%5,%6,%7}, {%8,%9}, {%0,%1,%2,%3};"
        : "+f"(c[0]), "+f"(c[1]), "+f"(c[2]), "+f"(c[3])
        : "r"(a[0]), "r"(a[1]), "r"(a[2]), "r"(a[3]),
          "r"(b0), "r"(b1));
}

__device__ __forceinline__ void ldsm_x4(unsigned& r0, unsigned& r1,
                                        unsigned& r2, unsigned& r3,
                                        uint32_t addr) {
    asm volatile("ldmatrix.sync.aligned.m8n8.x4.shared.b16 {%0,%1,%2,%3}, [%4];"
                 : "=r"(r0), "=r"(r1), "=r"(r2), "=r"(r3) : "r"(addr));
}

__device__ __forceinline__ void ldsm_x4_t(unsigned& r0, unsigned& r1,
                                          unsigned& r2, unsigned& r3,
                                          uint32_t addr) {
    asm volatile("ldmatrix.sync.aligned.m8n8.x4.trans.shared.b16 {%0,%1,%2,%3}, [%4];"
                 : "=r"(r0), "=r"(r1), "=r"(r2), "=r"(r3) : "r"(addr));
}

__device__ __forceinline__ unsigned packh2(float x, float y) {
    __half2 h = __floats2half2_rn(x, y);
    return *(unsigned*)&h;
}

__device__ __forceinline__ void cp_async16(void* smem_ptr, const void* gptr) {
    unsigned saddr = (unsigned)__cvta_generic_to_shared(smem_ptr);
    asm volatile("cp.async.cg.shared.global [%0], [%1], 16;\n"
                 :: "r"(saddr), "l"(gptr));
}
__device__ __forceinline__ void cp_commit() {
    asm volatile("cp.async.commit_group;\n");
}
__device__ __forceinline__ void cp_wait0() {
    asm volatile("cp.async.wait_group 0;\n");
}
__device__ __forceinline__ void cp_wait1() {
    asm volatile("cp.async.wait_group 1;\n");
}

// typed paired store
__device__ __forceinline__ void store2(float* p, float a, float b) {
    *(float2*)p = make_float2(a, b);
}
__device__ __forceinline__ void store2(__half* p, float a, float b) {
    *(__half2*)p = __floats2half2_rn(a, b);
}

// ---------------- prep: fp32 -> fp16 -------------------------------------------
__global__ void f2h_kernel(const float* __restrict__ in,
                           __half* __restrict__ out, int n8)
{
    int i = blockIdx.x * blockDim.x + threadIdx.x;
    if (i >= n8) return;
    const float4* ip = (const float4*)in + (size_t)i * 2;
    float4 a = ip[0], b = ip[1];
    uint4 o;
    o.x = packh2(a.x, a.y); o.y = packh2(a.z, a.w);
    o.z = packh2(b.x, b.y); o.w = packh2(b.z, b.w);
    *((uint4*)out + i) = o;
}

// ---------------- prep: 4 weight transposes in one launch ----------------------
__global__ void f2h_transpose4_kernel(
    const float* __restrict__ i0, __half* __restrict__ o0, int k0d, int n0d, int c0,
    const float* __restrict__ i1, __half* __restrict__ o1, int k1d, int n1d, int c1,
    const float* __restrict__ i2, __half* __restrict__ o2, int k2d, int n2d, int c2,
    const float* __restrict__ i3, __half* __restrict__ o3, int k3d, int n3d)
{
    __shared__ float t[32][33];
    int bidx = blockIdx.x;
    const float* in; __half* out; int Kdim, Ndim, lid;
    if (bidx < c0)      { in = i0; out = o0; Kdim = k0d; Ndim = n0d; lid = bidx; }
    else if (bidx < c1) { in = i1; out = o1; Kdim = k1d; Ndim = n1d; lid = bidx - c0; }
    else if (bidx < c2) { in = i2; out = o2; Kdim = k2d; Ndim = n2d; lid = bidx - c1; }
    else                { in = i3; out = o3; Kdim = k3d; Ndim = n3d; lid = bidx - c2; }

    int ntx = Ndim / 32;
    int n0 = (lid % ntx) * 32;
    int k0 = (lid / ntx) * 32;
    #pragma unroll
    for (int j = 0; j < 4; j++)
        t[threadIdx.y + j * 8][threadIdx.x] =
            in[(size_t)(k0 + threadIdx.y + j * 8) * Ndim + n0 + threadIdx.x];
    __syncthreads();
    #pragma unroll
    for (int j = 0; j < 4; j++)
        out[(size_t)(n0 + threadIdx.y + j * 8) * Kdim + k0 + threadIdx.x] =
            __float2half_rn(t[threadIdx.x][threadIdx.y + j * 8]);
}

// ---------------- pipelined FP16 GEMM (3-stage, ldmatrix), 3 segments ----------
#define HSTR 40
#define TILEH (128 * HSTR)
#define STGH  (2 * TILEH)
#define GEMM_SMEM (3 * STGH * 2)        // 61440 bytes

template <typename OutT>
__global__ __launch_bounds__(256) void h16_gemm3_kernel(
    const __half* __restrict__ A,
    const __half* __restrict__ B0, OutT* __restrict__ C0, int N0, int xs0,
    const __half* __restrict__ B1, OutT* __restrict__ C1, int N1, int xs1,
    const __half* __restrict__ B2, OutT* __restrict__ C2, int N2,
    int M, int K)
{
    extern __shared__ __half smh[];
    const uint32_t sbase = (uint32_t)__cvta_generic_to_shared(smh);

    const int bx = blockIdx.x;
    const __half* B; OutT* C; int N; int bxl;
    if (bx < xs0)      { B = B0; C = C0; N = N0; bxl = bx; }
    else if (bx < xs1) { B = B1; C = C1; N = N1; bxl = bx - xs0; }
    else               { B = B2; C = C2; N = N2; bxl = bx - xs1; }

    const int tid  = threadIdx.x;
    const int lane = tid & 31;
    const int warp = tid >> 5;
    const int wm   = (warp & 3) * 32;
    const int wn   = (warp >> 2) * 64;
    const int bm   = blockIdx.y * 128;
    const int bn   = bxl * 128;
    const int lq   = lane >> 2;
    const int lr   = lane & 3;

    const int arow_l = (lane & 7) + ((lane >> 3) & 1) * 8;
    const int awrd_l = (lane >> 4) * 4;
    const int brow_l = (lane & 7) + (lane >> 4) * 8;
    const int bwrd_l = ((lane >> 3) & 1) * 4;

    const int cr = tid >> 2;
    const int cc = tid & 3;

    float acc[2][8][4];
    #pragma unroll
    for (int i = 0; i < 2; i++)
        #pragma unroll
        for (int j = 0; j < 8; j++)
            #pragma unroll
            for (int r = 0; r < 4; r++) acc[i][j][r] = 0.f;

    const int T = K / 32;

    auto issue = [&](int t) {
        __half* sA = smh + (t % 3) * STGH;
        __half* sB = sA + TILEH;
        const int k0 = t * 32;
        #pragma unroll
        for (int i = 0; i < 2; i++) {
            int r = cr + i * 64;
            cp_async16(sA + r * HSTR + cc * 8, A + (size_t)(bm + r) * K + k0 + cc * 8);
            cp_async16(sB + r * HSTR + cc * 8, B + (size_t)(bn + r) * K + k0 + cc * 8);
        }
    };

    issue(0); cp_commit();
    issue(1); cp_commit();

    for (int t = 0; t < T; t++) {
        cp_wait1();
        __syncthreads();

        if (t + 2 < T) issue(t + 2);
        cp_commit();

        const uint32_t stA = sbase + (uint32_t)((t % 3) * STGH) * 2;
        const uint32_t stB = stA + TILEH * 2;
        #pragma unroll
        for (int ks = 0; ks < 2; ks++) {
            const int c8 = ks * 8;
            unsigned af[2][4];
            #pragma unroll
            for (int mi = 0; mi < 2; mi++)
                ldsm_x4(af[mi][0], af[mi][1], af[mi][2], af[mi][3],
                        stA + (uint32_t)(wm + mi * 16 + arow_l) * 80
                            + (uint32_t)(c8 + awrd_l) * 4);
            unsigned bf[8][2];
            #pragma unroll
            for (int nb = 0; nb < 8; nb += 2)
                ldsm_x4(bf[nb][0], bf[nb][1], bf[nb + 1][0], bf[nb + 1][1],
                        stB + (uint32_t)(wn + nb * 8 + brow_l) * 80
                            + (uint32_t)(c8 + bwrd_l) * 4);
            #pragma unroll
            for (int mi = 0; mi < 2; mi++)
                #pragma unroll
                for (int ni = 0; ni < 8; ni++)
                    mma_f16(acc[mi][ni], af[mi], bf[ni][0], bf[ni][1]);
        }
    }

    #pragma unroll
    for (int mi = 0; mi < 2; mi++) {
        int m = bm + wm + mi * 16 + lq;
        #pragma unroll
        for (int ni = 0; ni < 8; ni++) {
            int n = bn + wn + ni * 8 + lr * 2;
            store2(C + (size_t)m * N + n,       acc[mi][ni][0], acc[mi][ni][1]);
            store2(C + (size_t)(m + 8) * N + n, acc[mi][ni][2], acc[mi][ni][3]);
        }
    }
}

// ---------------- fused RoPE (half2 vectorized) ---------------------------------
__global__ void rope_fused_kernel(__half* __restrict__ qb, __half* __restrict__ kb,
                                  const float* __restrict__ cosf,
                                  const float* __restrict__ sinf,
                                  int tq, int total)
{
    int idx = blockIdx.x * blockDim.x + threadIdx.x;
    if (idx >= total) return;
    __half* t; int nheads; int li;
    if (idx < tq) { t = qb; nheads = NH;  li = idx; }
    else          { t = kb; nheads = NKV; li = idx - tq; }

    int i2  = li % 20;
    int h   = (li / 20) % nheads;
    int tok = li / (20 * nheads);
    int s   = tok % SEQ;
    int i   = i2 * 2;

    __half* p = t + (size_t)tok * nheads * HD + h * HD;
    float2 xa = __half22float2(*(__half2*)(p + i));
    float2 xb = __half22float2(*(__half2*)(p + i + 40));
    float2 c1 = *(const float2*)(cosf + s * HD + i);
    float2 s1 = *(const float2*)(sinf + s * HD + i);
    float2 c2 = *(const float2*)(cosf + s * HD + i + 40);
    float2 s2 = *(const float2*)(sinf + s * HD + i + 40);
    *(__half2*)(p + i)      = __floats2half2_rn(xa.x * c1.x - xb.x * s1.x,
                                                xa.y * c1.y - xb.y * s1.y);
    *(__half2*)(p + i + 40) = __floats2half2_rn(xb.x * c2.x + xa.x * s2.x,
                                                xb.y * c2.y + xa.y * s2.y);
}

// ---------------- FP16 flash attention: KT=128, double-buffered K/V ------------
// Q/K/V rows: 80 halves padded to 88 (176B; 44 words ==12 mod 32 -> conflict-free).
// V stored NATURAL row-major; PV B-fragments via ldmatrix.trans (HW transpose).
// P rows: 76 words (304B; ==12 mod 32).
#define QWD 44                 // Q/K/V row stride in words
#define PWD 76                 // P row stride in words
#define KVW (128 * QWD)        // words per K or V buffer = 5632
#define ATT_WORDS3 (KVW + 2 * KVW + 2 * KVW + 128 * PWD)   // 37888 words
#define ATT_SMEM3  (ATT_WORDS3 * 4)                        // 151552 bytes

__global__ __launch_bounds__(256) void attn_h16_kernel(
    const __half* __restrict__ q, const __half* __restrict__ k,
    const __half* __restrict__ v, __half* __restrict__ oh)
{
    extern __shared__ unsigned sw[];
    __half* Qh = (__half*)sw;
    unsigned* Pw = sw + 5 * KVW;
    const uint32_t sbase = (uint32_t)__cvta_generic_to_shared(sw);
    const uint32_t Qb = sbase;
    const uint32_t Kb0 = sbase + KVW * 4;          // +22528
    const uint32_t Vb0 = sbase + 3 * KVW * 4;      // +67584
    const uint32_t Pb  = sbase + 5 * KVW * 4;      // +112640

    const int b    = blockIdx.z;
    const int h    = blockIdx.y;
    const int qt   = gridDim.x - 1 - blockIdx.x;   // longest blocks first
    const int kvh  = h >> 2;
    const int tid  = threadIdx.x;
    const int lane = tid & 31;
    const int warp = tid >> 5;
    const int lq   = lane >> 2;
    const int lr   = lane & 3;
    const int wr   = warp * 16;
    const float scale = rsqrtf((float)HD);

    const int arow_l = (lane & 7) + ((lane >> 3) & 1) * 8;
    const int awrd_l = (lane >> 4) * 4;
    const int brow_l = (lane & 7) + (lane >> 4) * 8;
    const int bwrd_l = ((lane >> 3) & 1) * 4;
    // trans-ldmatrix lane map for V (rows = keys, cols = d)
    const int vrow_l = (lane & 7) + ((lane >> 3) & 1) * 8;
    const int vcol_l = (lane >> 4) * 8;

    // copy coords (1280 chunks per tile, 5 per thread)
    // f = tid + i*256 -> row = f/10, ch = f%10

    // ---- Q load (group 0) ----
    {
        const __half* qsrc = q + ((size_t)(b * SEQ + qt * 128)) * (NH * HD) + h * HD;
        #pragma unroll
        for (int i = 0; i < 5; i++) {
            int f = tid + i * 256;
            int row = f / 10, ch = f % 10;
            cp_async16(Qh + row * (2 * QWD) + ch * 8,
                       qsrc + (size_t)row * (NH * HD) + ch * 8);
        }
        cp_commit();
    }

    auto issue_kv = [&](int kt) {
        __half* Kh = (__half*)(sw + KVW + (kt & 1) * KVW);
        __half* Vh = (__half*)(sw + 3 * KVW + (kt & 1) * KVW);
        const __half* ksrc = k + ((size_t)(b * SEQ + kt * 128)) * (NKV * HD) + kvh * HD;
        const __half* vsrc = v + ((size_t)(b * SEQ + kt * 128)) * (NKV * HD) + kvh * HD;
        #pragma unroll
        for (int i = 0; i < 5; i++) {
            int f = tid + i * 256;
            int row = f / 10, ch = f % 10;
            cp_async16(Kh + row * (2 * QWD) + ch * 8,
                       ksrc + (size_t)row * (NKV * HD) + ch * 8);
            cp_async16(Vh + row * (2 * QWD) + ch * 8,
                       vsrc + (size_t)row * (NKV * HD) + ch * 8);
        }
    };

    issue_kv(0); cp_commit();   // group 1

    float oacc[10][4];
    #pragma unroll
    for (int i = 0; i < 10; i++)
        #pragma unroll
        for (int j = 0; j < 4; j++) oacc[i][j] = 0.f;
    float m0 = -INFINITY, m1 = -INFINITY;
    float l0 = 0.f, l1 = 0.f;

    const int row0 = qt * 128 + wr + lq;
    const int row1 = row0 + 8;

    for (int kt = 0; kt <= qt; kt++) {
        // prefetch next tile into the other buffer
        if (kt + 1 <= qt) issue_kv(kt + 1);
        cp_commit();
        if (kt + 1 <= qt) cp_wait1(); else cp_wait0();
        __syncthreads();            // tile kt resident for all warps

        const uint32_t Kb = Kb0 + (uint32_t)(kt & 1) * (KVW * 4);
        const uint32_t Vb = Vb0 + (uint32_t)(kt & 1) * (KVW * 4);

        // ---- QK^T: S[16 x 128] per warp, 5 k-steps of 16 ----
        float sc[16][4];
        #pragma unroll
        for (int ni = 0; ni < 16; ni++)
            #pragma unroll
            for (int j = 0; j < 4; j++) sc[ni][j] = 0.f;

        #pragma unroll
        for (int ks = 0; ks < 5; ks++) {
            const int c8 = ks * 8;
            unsigned af[4];
            ldsm_x4(af[0], af[1], af[2], af[3],
                    Qb + (uint32_t)(wr + arow_l) * 176 + (uint32_t)(c8 + awrd_l) * 4);
            unsigned bf[16][2];
            #pragma unroll
            for (int nb = 0; nb < 16; nb += 2)
                ldsm_x4(bf[nb][0], bf[nb][1], bf[nb + 1][0], bf[nb + 1][1],
                        Kb + (uint32_t)(nb * 8 + brow_l) * 176
                           + (uint32_t)(c8 + bwrd_l) * 4);
            #pragma unroll
            for (int ni = 0; ni < 16; ni++)
                mma_f16(sc[ni], af, bf[ni][0], bf[ni][1]);
        }

        // ---- scale + causal mask ----
        const bool diag = (kt == qt);
        #pragma unroll
        for (int ni = 0; ni < 16; ni++) {
            int c = kt * 128 + ni * 8 + lr * 2;
            sc[ni][0] = (diag && c     > row0) ? -1e30f : sc[ni][0] * scale;
            sc[ni][1] = (diag && c + 1 > row0) ? -1e30f : sc[ni][1] * scale;
            sc[ni][2] = (diag && c     > row1) ? -1e30f : sc[ni][2] * scale;
            sc[ni][3] = (diag && c + 1 > row1) ? -1e30f : sc[ni][3] * scale;
        }

        // ---- online softmax ----
        float rm0 = -1e30f, rm1 = -1e30f;
        #pragma unroll
        for (int ni = 0; ni < 16; ni++) {
            rm0 = fmaxf(rm0, fmaxf(sc[ni][0], sc[ni][1]));
            rm1 = fmaxf(rm1, fmaxf(sc[ni][2], sc[ni][3]));
        }
        rm0 = fmaxf(rm0, __shfl_xor_sync(0xffffffffu, rm0, 1));
        rm0 = fmaxf(rm0, __shfl_xor_sync(0xffffffffu, rm0, 2));
        rm1 = fmaxf(rm1, __shfl_xor_sync(0xffffffffu, rm1, 1));
        rm1 = fmaxf(rm1, __shfl_xor_sync(0xffffffffu, rm1, 2));

        float m0n = fmaxf(m0, rm0);
        float m1n = fmaxf(m1, rm1);
        float a0  = __expf(m0 - m0n);
        float a1  = __expf(m1 - m1n);
        m0 = m0n; m1 = m1n;

        float rs0 = 0.f, rs1 = 0.f;
        #pragma unroll
        for (int ni = 0; ni < 16; ni++) {
            float p0 = __expf(sc[ni][0] - m0n);
            float p1 = __expf(sc[ni][1] - m0n);
            float p2 = __expf(sc[ni][2] - m1n);
            float p3 = __expf(sc[ni][3] - m1n);
            rs0 += p0 + p1;
            rs1 += p2 + p3;
            Pw[(wr + lq    ) * PWD + ni * 4 + lr] = packh2(p0, p1);
            Pw[(wr + lq + 8) * PWD + ni * 4 + lr] = packh2(p2, p3);
        }
        rs0 += __shfl_xor_sync(0xffffffffu, rs0, 1);
        rs0 += __shfl_xor_sync(0xffffffffu, rs0, 2);
        rs1 += __shfl_xor_sync(0xffffffffu, rs1, 1);
        rs1 += __shfl_xor_sync(0xffffffffu, rs1, 2);
        l0 = l0 * a0 + rs0;
        l1 = l1 * a1 + rs1;

        #pragma unroll
        for (int ni = 0; ni < 10; ni++) {
            oacc[ni][0] *= a0; oacc[ni][1] *= a0;
            oacc[ni][2] *= a1; oacc[ni][3] *= a1;
        }

        __syncwarp();   // Ps rows are warp-private

        // ---- PV: O[16 x 80] += P[16 x 128] @ V[128 x 80]; V via ldmatrix.trans --
        #pragma unroll
        for (int ks = 0; ks < 8; ks++) {
            const int c8 = ks * 8;
            unsigned af[4];
            ldsm_x4(af[0], af[1], af[2], af[3],
                    Pb + (uint32_t)(wr + arow_l) * 304 + (uint32_t)(c8 + awrd_l) * 4);
            unsigned bf[10][2];
            #pragma unroll
            for (int nb = 0; nb < 10; nb += 2)
                ldsm_x4_t(bf[nb][0], bf[nb][1], bf[nb + 1][0], bf[nb + 1][1],
                          Vb + (uint32_t)(ks * 16 + vrow_l) * 176
                             + (uint32_t)(nb * 8 + vcol_l) * 2);
            #pragma unroll
            for (int ni = 0; ni < 10; ni++)
                mma_f16(oacc[ni], af, bf[ni][0], bf[ni][1]);
        }
        __syncthreads();   // protect buf (kt&1) before re-issue at kt+2
    }

    // ---- epilogue: fp16 output feeds the fp16 Wo GEMM ----
    const float inv0 = 1.0f / l0;
    const float inv1 = 1.0f / l1;
    #pragma unroll
    for (int ni = 0; ni < 10; ni++) {
        int c = ni * 8 + lr * 2;
        __half2* p0 = (__half2*)(oh + (size_t)(b * SEQ + row0) * (NH * HD) + h * HD + c);
        __half2* p1 = (__half2*)(oh + (size_t)(b * SEQ + row1) * (NH * HD) + h * HD + c);
        *p0 = __floats2half2_rn(oacc[ni][0] * inv0, oacc[ni][1] * inv0);
        *p1 = __floats2half2_rn(oacc[ni][2] * inv1, oacc[ni][3] * inv1);
    }
}

// ---------------- launch --------------------------------------------------------
extern "C" void kernel_launch(void* const* d_in, const int* in_sizes, int n_in,
                              void* d_out, int out_size)
{
    const float* x    = (const float*)d_in[0];
    const float* cosf = (const float*)d_in[1];
    const float* sinf = (const float*)d_in[2];
    const float* Wq   = (const float*)d_in[3];
    const float* Wk   = (const float*)d_in[4];
    const float* Wv   = (const float*)d_in[5];
    const float* Wo   = (const float*)d_in[6];
    float* out = (float*)d_out;

    __half *qhb, *khb, *vhb, *ohb, *xh, *wqh, *wkh, *wvh, *woh;
    cudaGetSymbolAddress((void**)&qhb, g_qh);
    cudaGetSymbolAddress((void**)&khb, g_kh);
    cudaGetSymbolAddress((void**)&vhb, g_vh);
    cudaGetSymbolAddress((void**)&ohb, g_oh);
    cudaGetSymbolAddress((void**)&xh, g_xh);
    cudaGetSymbolAddress((void**)&wqh, g_wqh);
    cudaGetSymbolAddress((void**)&wkh, g_wkh);
    cudaGetSymbolAddress((void**)&wvh, g_wvh);
    cudaGetSymbolAddress((void**)&woh, g_woh);

    // prep: x -> half; 4 weight transposes in one launch
    {
        int n8 = M_TOK * HIDDEN / 8;
        f2h_kernel<<<(n8 + 255) / 256, 256>>>(x, xh, n8);
        int c0 = 6400, c1 = c0 + 1600, c2 = c1 + 1600, ctot = c2 + 6400;
        dim3 blk(32, 8);
        f2h_transpose4_kernel<<<ctot, blk>>>(
            Wq, wqh, HIDDEN, NH * HD, c0,
            Wk, wkh, HIDDEN, NKV * HD, c1,
            Wv, wvh, HIDDEN, NKV * HD, c2,
            Wo, woh, NH * HD, HIDDEN);
    }

    cudaFuncSetAttribute(h16_gemm3_kernel<__half>,
                         cudaFuncAttributeMaxDynamicSharedMemorySize, GEMM_SMEM);
    cudaFuncSetAttribute(h16_gemm3_kernel<float>,
                         cudaFuncAttributeMaxDynamicSharedMemorySize, GEMM_SMEM);

    // fused Q/K/V projections (fp16 mma, half outputs)
    {
        dim3 g(30, M_TOK / 128);
        h16_gemm3_kernel<__half><<<g, 256, GEMM_SMEM>>>(
            xh,
            wqh, qhb, NH * HD, 20,
            wkh, khb, NKV * HD, 25,
            wvh, vhb, NKV * HD,
            M_TOK, HIDDEN);
    }

    // fused RoPE (half2)
    {
        int tq = M_TOK * NH * 20;
        int tk = M_TOK * NKV * 20;
        int tot = tq + tk;
        rope_fused_kernel<<<(tot + 255) / 256, 256>>>(qhb, khb, cosf, sinf, tq, tot);
    }

    // attention (fp16 mma flash, KT=128, double-buffered, trans-V)
    {
        cudaFuncSetAttribute(attn_h16_kernel,
                             cudaFuncAttributeMaxDynamicSharedMemorySize, ATT_SMEM3);
        dim3 ga(SEQ / 128, NH, BATCH);
        attn_h16_kernel<<<ga, 256, ATT_SMEM3>>>(qhb, khb, vhb, ohb);
    }

    // output projection (fp16 mma, fp32 output)
    {
        dim3 go(HIDDEN / 128, M_TOK / 128);
        h16_gemm3_kernel<float><<<go, 256, GEMM_SMEM>>>(
            ohb,
            woh, out, HIDDEN, 20,
            woh, out, HIDDEN, 20,
            woh, out, HIDDEN,
            M_TOK, HIDDEN);
    }
}

// round 14
// speedup vs baseline: 1.8575x; 1.0824x over previous
#include <cuda_runtime.h>
#include <cuda_fp16.h>
#include <math.h>
#include <stdint.h>

#define HIDDEN 2560
#define NH 32
#define NKV 8
#define HD 80
#define BATCH 2
#define SEQ 2048
#define M_TOK (BATCH * SEQ)   // 4096

// ---------------- scratch (static device globals; no runtime alloc) ----------
__device__ __half g_qh[M_TOK * NH * HD];
__device__ __half g_kh[M_TOK * NKV * HD];
__device__ __half g_vh[M_TOK * NKV * HD];
__device__ __half g_oh[M_TOK * NH * HD];       // attn out, half, K-major
__device__ __half g_xh[M_TOK * HIDDEN];        // x rounded to half
__device__ __half g_wqh[HIDDEN * NH * HD];     // weights: transposed [N,K] half
__device__ __half g_wkh[HIDDEN * NKV * HD];
__device__ __half g_wvh[HIDDEN * NKV * HD];
__device__ __half g_woh[NH * HD * HIDDEN];

__device__ __forceinline__ void mma_f16(float* c, const unsigned* a,
                                        unsigned b0, unsigned b1) {
    asm volatile(
        "mma.sync.aligned.m16n8k16.row.col.f32.f16.f16.f32 "
        "{%0,%1,%2,%3}, {%4,%5,%6,%7}, {%8,%9}, {%0,%1,%2,%3};"
        : "+f"(c[0]), "+f"(c[1]), "+f"(c[2]), "+f"(c[3])
        : "r"(a[0]), "r"(a[1]), "r"(a[2]), "r"(a[3]),
          "r"(b0), "r"(b1));
}

__device__ __forceinline__ void ldsm_x4(unsigned& r0, unsigned& r1,
                                        unsigned& r2, unsigned& r3,
                                        uint32_t addr) {
    asm volatile("ldmatrix.sync.aligned.m8n8.x4.shared.b16 {%0,%1,%2,%3}, [%4];"
                 : "=r"(r0), "=r"(r1), "=r"(r2), "=r"(r3) : "r"(addr));
}

__device__ __forceinline__ void ldsm_x4_t(unsigned& r0, unsigned& r1,
                                          unsigned& r2, unsigned& r3,
                                          uint32_t addr) {
    asm volatile("ldmatrix.sync.aligned.m8n8.x4.trans.shared.b16 {%0,%1,%2,%3}, [%4];"
                 : "=r"(r0), "=r"(r1), "=r"(r2), "=r"(r3) : "r"(addr));
}

__device__ __forceinline__ unsigned packh2(float x, float y) {
    __half2 h = __floats2half2_rn(x, y);
    return *(unsigned*)&h;
}

__device__ __forceinline__ void cp_async16(void* smem_ptr, const void* gptr) {
    unsigned saddr = (unsigned)__cvta_generic_to_shared(smem_ptr);
    asm volatile("cp.async.cg.shared.global [%0], [%1], 16;\n"
                 :: "r"(saddr), "l"(gptr));
}
__device__ __forceinline__ void cp_commit() {
    asm volatile("cp.async.commit_group;\n");
}
__device__ __forceinline__ void cp_wait0() {
    asm volatile("cp.async.wait_group 0;\n");
}
__device__ __forceinline__ void cp_wait1() {
    asm volatile("cp.async.wait_group 1;\n");
}

// typed paired store
__device__ __forceinline__ void store2(float* p, float a, float b) {
    *(float2*)p = make_float2(a, b);
}
__device__ __forceinline__ void store2(__half* p, float a, float b) {
    *(__half2*)p = __floats2half2_rn(a, b);
}

// ---------------- prep: fp32 -> fp16 -------------------------------------------
__global__ void f2h_kernel(const float* __restrict__ in,
                           __half* __restrict__ out, int n8)
{
    int i = blockIdx.x * blockDim.x + threadIdx.x;
    if (i >= n8) return;
    const float4* ip = (const float4*)in + (size_t)i * 2;
    float4 a = ip[0], b = ip[1];
    uint4 o;
    o.x = packh2(a.x, a.y); o.y = packh2(a.z, a.w);
    o.z = packh2(b.x, b.y); o.w = packh2(b.z, b.w);
    *((uint4*)out + i) = o;
}

// ---------------- prep: 4 weight transposes in one launch ----------------------
__global__ void f2h_transpose4_kernel(
    const float* __restrict__ i0, __half* __restrict__ o0, int k0d, int n0d, int c0,
    const float* __restrict__ i1, __half* __restrict__ o1, int k1d, int n1d, int c1,
    const float* __restrict__ i2, __half* __restrict__ o2, int k2d, int n2d, int c2,
    const float* __restrict__ i3, __half* __restrict__ o3, int k3d, int n3d)
{
    __shared__ float t[32][33];
    int bidx = blockIdx.x;
    const float* in; __half* out; int Kdim, Ndim, lid;
    if (bidx < c0)      { in = i0; out = o0; Kdim = k0d; Ndim = n0d; lid = bidx; }
    else if (bidx < c1) { in = i1; out = o1; Kdim = k1d; Ndim = n1d; lid = bidx - c0; }
    else if (bidx < c2) { in = i2; out = o2; Kdim = k2d; Ndim = n2d; lid = bidx - c1; }
    else                { in = i3; out = o3; Kdim = k3d; Ndim = n3d; lid = bidx - c2; }

    int ntx = Ndim / 32;
    int n0 = (lid % ntx) * 32;
    int k0 = (lid / ntx) * 32;
    #pragma unroll
    for (int j = 0; j < 4; j++)
        t[threadIdx.y + j * 8][threadIdx.x] =
            in[(size_t)(k0 + threadIdx.y + j * 8) * Ndim + n0 + threadIdx.x];
    __syncthreads();
    #pragma unroll
    for (int j = 0; j < 4; j++)
        out[(size_t)(n0 + threadIdx.y + j * 8) * Kdim + k0 + threadIdx.x] =
            __float2half_rn(t[threadIdx.x][threadIdx.y + j * 8]);
}

// ---------------- pipelined FP16 GEMM (BK=64, 3-stage, ldmatrix), 3 segments ---
// Rows padded: 64 halves -> 72 (144B; 36 words == 4 mod 32 -> conflict-free).
#define HSTR 72
#define TILEH (128 * HSTR)              // halves per operand tile = 9216
#define STGH  (2 * TILEH)               // halves per stage = 18432
#define GEMM_SMEM (3 * STGH * 2)        // 110592 bytes

template <typename OutT>
__global__ __launch_bounds__(256) void h16_gemm3_kernel(
    const __half* __restrict__ A,
    const __half* __restrict__ B0, OutT* __restrict__ C0, int N0, int xs0,
    const __half* __restrict__ B1, OutT* __restrict__ C1, int N1, int xs1,
    const __half* __restrict__ B2, OutT* __restrict__ C2, int N2,
    int M, int K)
{
    extern __shared__ __half smh[];
    const uint32_t sbase = (uint32_t)__cvta_generic_to_shared(smh);

    const int bx = blockIdx.x;
    const __half* B; OutT* C; int N; int bxl;
    if (bx < xs0)      { B = B0; C = C0; N = N0; bxl = bx; }
    else if (bx < xs1) { B = B1; C = C1; N = N1; bxl = bx - xs0; }
    else               { B = B2; C = C2; N = N2; bxl = bx - xs1; }

    const int tid  = threadIdx.x;
    const int lane = tid & 31;
    const int warp = tid >> 5;
    const int wm   = (warp & 3) * 32;
    const int wn   = (warp >> 2) * 64;
    const int bm   = blockIdx.y * 128;
    const int bn   = bxl * 128;
    const int lq   = lane >> 2;
    const int lr   = lane & 3;

    const int arow_l = (lane & 7) + ((lane >> 3) & 1) * 8;
    const int awrd_l = (lane >> 4) * 4;
    const int brow_l = (lane & 7) + (lane >> 4) * 8;
    const int bwrd_l = ((lane >> 3) & 1) * 4;

    const int cr = tid >> 3;            // 0..31 (+32*i), 4 chunks/thread/operand
    const int cc = tid & 7;             // 16B chunk in 64-half row

    float acc[2][8][4];
    #pragma unroll
    for (int i = 0; i < 2; i++)
        #pragma unroll
        for (int j = 0; j < 8; j++)
            #pragma unroll
            for (int r = 0; r < 4; r++) acc[i][j][r] = 0.f;

    const int T = K / 64;

    auto issue = [&](int t) {
        __half* sA = smh + (t % 3) * STGH;
        __half* sB = sA + TILEH;
        const int k0 = t * 64;
        #pragma unroll
        for (int i = 0; i < 4; i++) {
            int r = cr + i * 32;
            cp_async16(sA + r * HSTR + cc * 8, A + (size_t)(bm + r) * K + k0 + cc * 8);
            cp_async16(sB + r * HSTR + cc * 8, B + (size_t)(bn + r) * K + k0 + cc * 8);
        }
    };

    issue(0); cp_commit();
    issue(1); cp_commit();

    for (int t = 0; t < T; t++) {
        cp_wait1();
        __syncthreads();

        if (t + 2 < T) issue(t + 2);
        cp_commit();

        const uint32_t stA = sbase + (uint32_t)((t % 3) * STGH) * 2;
        const uint32_t stB = stA + TILEH * 2;
        #pragma unroll
        for (int ks = 0; ks < 4; ks++) {
            const int c8 = ks * 8;
            unsigned af[2][4];
            #pragma unroll
            for (int mi = 0; mi < 2; mi++)
                ldsm_x4(af[mi][0], af[mi][1], af[mi][2], af[mi][3],
                        stA + (uint32_t)(wm + mi * 16 + arow_l) * 144
                            + (uint32_t)(c8 + awrd_l) * 4);
            unsigned bf[8][2];
            #pragma unroll
            for (int nb = 0; nb < 8; nb += 2)
                ldsm_x4(bf[nb][0], bf[nb][1], bf[nb + 1][0], bf[nb + 1][1],
                        stB + (uint32_t)(wn + nb * 8 + brow_l) * 144
                            + (uint32_t)(c8 + bwrd_l) * 4);
            #pragma unroll
            for (int mi = 0; mi < 2; mi++)
                #pragma unroll
                for (int ni = 0; ni < 8; ni++)
                    mma_f16(acc[mi][ni], af[mi], bf[ni][0], bf[ni][1]);
        }
    }

    #pragma unroll
    for (int mi = 0; mi < 2; mi++) {
        int m = bm + wm + mi * 16 + lq;
        #pragma unroll
        for (int ni = 0; ni < 8; ni++) {
            int n = bn + wn + ni * 8 + lr * 2;
            store2(C + (size_t)m * N + n,       acc[mi][ni][0], acc[mi][ni][1]);
            store2(C + (size_t)(m + 8) * N + n, acc[mi][ni][2], acc[mi][ni][3]);
        }
    }
}

// ---------------- fused RoPE (half2 vectorized) ---------------------------------
__global__ void rope_fused_kernel(__half* __restrict__ qb, __half* __restrict__ kb,
                                  const float* __restrict__ cosf,
                                  const float* __restrict__ sinf,
                                  int tq, int total)
{
    int idx = blockIdx.x * blockDim.x + threadIdx.x;
    if (idx >= total) return;
    __half* t; int nheads; int li;
    if (idx < tq) { t = qb; nheads = NH;  li = idx; }
    else          { t = kb; nheads = NKV; li = idx - tq; }

    int i2  = li % 20;
    int h   = (li / 20) % nheads;
    int tok = li / (20 * nheads);
    int s   = tok % SEQ;
    int i   = i2 * 2;

    __half* p = t + (size_t)tok * nheads * HD + h * HD;
    float2 xa = __half22float2(*(__half2*)(p + i));
    float2 xb = __half22float2(*(__half2*)(p + i + 40));
    float2 c1 = *(const float2*)(cosf + s * HD + i);
    float2 s1 = *(const float2*)(sinf + s * HD + i);
    float2 c2 = *(const float2*)(cosf + s * HD + i + 40);
    float2 s2 = *(const float2*)(sinf + s * HD + i + 40);
    *(__half2*)(p + i)      = __floats2half2_rn(xa.x * c1.x - xb.x * s1.x,
                                                xa.y * c1.y - xb.y * s1.y);
    *(__half2*)(p + i + 40) = __floats2half2_rn(xb.x * c2.x + xa.x * s2.x,
                                                xb.y * c2.y + xa.y * s2.y);
}

// ---------------- FP16 flash attention: KT=128, double-buffered K/V ------------
#define QWD 44                 // Q/K/V row stride in words
#define PWD 76                 // P row stride in words
#define KVW (128 * QWD)        // words per K or V buffer = 5632
#define ATT_WORDS3 (KVW + 2 * KVW + 2 * KVW + 128 * PWD)   // 37888 words
#define ATT_SMEM3  (ATT_WORDS3 * 4)                        // 151552 bytes

__global__ __launch_bounds__(256) void attn_h16_kernel(
    const __half* __restrict__ q, const __half* __restrict__ k,
    const __half* __restrict__ v, __half* __restrict__ oh)
{
    extern __shared__ unsigned sw[];
    __half* Qh = (__half*)sw;
    unsigned* Pw = sw + 5 * KVW;
    const uint32_t sbase = (uint32_t)__cvta_generic_to_shared(sw);
    const uint32_t Qb = sbase;
    const uint32_t Kb0 = sbase + KVW * 4;
    const uint32_t Vb0 = sbase + 3 * KVW * 4;
    const uint32_t Pb  = sbase + 5 * KVW * 4;

    const int b    = blockIdx.z;
    const int h    = blockIdx.y;
    const int qt   = gridDim.x - 1 - blockIdx.x;
    const int kvh  = h >> 2;
    const int tid  = threadIdx.x;
    const int lane = tid & 31;
    const int warp = tid >> 5;
    const int lq   = lane >> 2;
    const int lr   = lane & 3;
    const int wr   = warp * 16;
    const float scale = rsqrtf((float)HD);

    const int arow_l = (lane & 7) + ((lane >> 3) & 1) * 8;
    const int awrd_l = (lane >> 4) * 4;
    const int brow_l = (lane & 7) + (lane >> 4) * 8;
    const int bwrd_l = ((lane >> 3) & 1) * 4;
    const int vrow_l = (lane & 7) + ((lane >> 3) & 1) * 8;
    const int vcol_l = (lane >> 4) * 8;

    // ---- Q load ----
    {
        const __half* qsrc = q + ((size_t)(b * SEQ + qt * 128)) * (NH * HD) + h * HD;
        #pragma unroll
        for (int i = 0; i < 5; i++) {
            int f = tid + i * 256;
            int row = f / 10, ch = f % 10;
            cp_async16(Qh + row * (2 * QWD) + ch * 8,
                       qsrc + (size_t)row * (NH * HD) + ch * 8);
        }
        cp_commit();
    }

    auto issue_kv = [&](int kt) {
        __half* Kh = (__half*)(sw + KVW + (kt & 1) * KVW);
        __half* Vh = (__half*)(sw + 3 * KVW + (kt & 1) * KVW);
        const __half* ksrc = k + ((size_t)(b * SEQ + kt * 128)) * (NKV * HD) + kvh * HD;
        const __half* vsrc = v + ((size_t)(b * SEQ + kt * 128)) * (NKV * HD) + kvh * HD;
        #pragma unroll
        for (int i = 0; i < 5; i++) {
            int f = tid + i * 256;
            int row = f / 10, ch = f % 10;
            cp_async16(Kh + row * (2 * QWD) + ch * 8,
                       ksrc + (size_t)row * (NKV * HD) + ch * 8);
            cp_async16(Vh + row * (2 * QWD) + ch * 8,
                       vsrc + (size_t)row * (NKV * HD) + ch * 8);
        }
    };

    issue_kv(0); cp_commit();

    float oacc[10][4];
    #pragma unroll
    for (int i = 0; i < 10; i++)
        #pragma unroll
        for (int j = 0; j < 4; j++) oacc[i][j] = 0.f;
    float m0 = -INFINITY, m1 = -INFINITY;
    float l0 = 0.f, l1 = 0.f;

    const int row0 = qt * 128 + wr + lq;
    const int row1 = row0 + 8;

    for (int kt = 0; kt <= qt; kt++) {
        if (kt + 1 <= qt) issue_kv(kt + 1);
        cp_commit();
        if (kt + 1 <= qt) cp_wait1(); else cp_wait0();
        __syncthreads();

        const uint32_t Kb = Kb0 + (uint32_t)(kt & 1) * (KVW * 4);
        const uint32_t Vb = Vb0 + (uint32_t)(kt & 1) * (KVW * 4);

        // ---- QK^T ----
        float sc[16][4];
        #pragma unroll
        for (int ni = 0; ni < 16; ni++)
            #pragma unroll
            for (int j = 0; j < 4; j++) sc[ni][j] = 0.f;

        #pragma unroll
        for (int ks = 0; ks < 5; ks++) {
            const int c8 = ks * 8;
            unsigned af[4];
            ldsm_x4(af[0], af[1], af[2], af[3],
                    Qb + (uint32_t)(wr + arow_l) * 176 + (uint32_t)(c8 + awrd_l) * 4);
            unsigned bf[16][2];
            #pragma unroll
            for (int nb = 0; nb < 16; nb += 2)
                ldsm_x4(bf[nb][0], bf[nb][1], bf[nb + 1][0], bf[nb + 1][1],
                        Kb + (uint32_t)(nb * 8 + brow_l) * 176
                           + (uint32_t)(c8 + bwrd_l) * 4);
            #pragma unroll
            for (int ni = 0; ni < 16; ni++)
                mma_f16(sc[ni], af, bf[ni][0], bf[ni][1]);
        }

        // ---- scale + causal mask ----
        const bool diag = (kt == qt);
        #pragma unroll
        for (int ni = 0; ni < 16; ni++) {
            int c = kt * 128 + ni * 8 + lr * 2;
            sc[ni][0] = (diag && c     > row0) ? -1e30f : sc[ni][0] * scale;
            sc[ni][1] = (diag && c + 1 > row0) ? -1e30f : sc[ni][1] * scale;
            sc[ni][2] = (diag && c     > row1) ? -1e30f : sc[ni][2] * scale;
            sc[ni][3] = (diag && c + 1 > row1) ? -1e30f : sc[ni][3] * scale;
        }

        // ---- online softmax ----
        float rm0 = -1e30f, rm1 = -1e30f;
        #pragma unroll
        for (int ni = 0; ni < 16; ni++) {
            rm0 = fmaxf(rm0, fmaxf(sc[ni][0], sc[ni][1]));
            rm1 = fmaxf(rm1, fmaxf(sc[ni][2], sc[ni][3]));
        }
        rm0 = fmaxf(rm0, __shfl_xor_sync(0xffffffffu, rm0, 1));
        rm0 = fmaxf(rm0, __shfl_xor_sync(0xffffffffu, rm0, 2));
        rm1 = fmaxf(rm1, __shfl_xor_sync(0xffffffffu, rm1, 1));
        rm1 = fmaxf(rm1, __shfl_xor_sync(0xffffffffu, rm1, 2));

        float m0n = fmaxf(m0, rm0);
        float m1n = fmaxf(m1, rm1);
        float a0  = __expf(m0 - m0n);
        float a1  = __expf(m1 - m1n);
        m0 = m0n; m1 = m1n;

        float rs0 = 0.f, rs1 = 0.f;
        #pragma unroll
        for (int ni = 0; ni < 16; ni++) {
            float p0 = __expf(sc[ni][0] - m0n);
            float p1 = __expf(sc[ni][1] - m0n);
            float p2 = __expf(sc[ni][2] - m1n);
            float p3 = __expf(sc[ni][3] - m1n);
            rs0 += p0 + p1;
            rs1 += p2 + p3;
            Pw[(wr + lq    ) * PWD + ni * 4 + lr] = packh2(p0, p1);
            Pw[(wr + lq + 8) * PWD + ni * 4 + lr] = packh2(p2, p3);
        }
        rs0 += __shfl_xor_sync(0xffffffffu, rs0, 1);
        rs0 += __shfl_xor_sync(0xffffffffu, rs0, 2);
        rs1 += __shfl_xor_sync(0xffffffffu, rs1, 1);
        rs1 += __shfl_xor_sync(0xffffffffu, rs1, 2);
        l0 = l0 * a0 + rs0;
        l1 = l1 * a1 + rs1;

        #pragma unroll
        for (int ni = 0; ni < 10; ni++) {
            oacc[ni][0] *= a0; oacc[ni][1] *= a0;
            oacc[ni][2] *= a1; oacc[ni][3] *= a1;
        }

        __syncwarp();

        // ---- PV (V via ldmatrix.trans) ----
        #pragma unroll
        for (int ks = 0; ks < 8; ks++) {
            const int c8 = ks * 8;
            unsigned af[4];
            ldsm_x4(af[0], af[1], af[2], af[3],
                    Pb + (uint32_t)(wr + arow_l) * 304 + (uint32_t)(c8 + awrd_l) * 4);
            unsigned bf[10][2];
            #pragma unroll
            for (int nb = 0; nb < 10; nb += 2)
                ldsm_x4_t(bf[nb][0], bf[nb][1], bf[nb + 1][0], bf[nb + 1][1],
                          Vb + (uint32_t)(ks * 16 + vrow_l) * 176
                             + (uint32_t)(nb * 8 + vcol_l) * 2);
            #pragma unroll
            for (int ni = 0; ni < 10; ni++)
                mma_f16(oacc[ni], af, bf[ni][0], bf[ni][1]);
        }
        __syncthreads();
    }

    // ---- epilogue ----
    const float inv0 = 1.0f / l0;
    const float inv1 = 1.0f / l1;
    #pragma unroll
    for (int ni = 0; ni < 10; ni++) {
        int c = ni * 8 + lr * 2;
        __half2* p0 = (__half2*)(oh + (size_t)(b * SEQ + row0) * (NH * HD) + h * HD + c);
        __half2* p1 = (__half2*)(oh + (size_t)(b * SEQ + row1) * (NH * HD) + h * HD + c);
        *p0 = __floats2half2_rn(oacc[ni][0] * inv0, oacc[ni][1] * inv0);
        *p1 = __floats2half2_rn(oacc[ni][2] * inv1, oacc[ni][3] * inv1);
    }
}

// ---------------- launch --------------------------------------------------------
extern "C" void kernel_launch(void* const* d_in, const int* in_sizes, int n_in,
                              void* d_out, int out_size)
{
    const float* x    = (const float*)d_in[0];
    const float* cosf = (const float*)d_in[1];
    const float* sinf = (const float*)d_in[2];
    const float* Wq   = (const float*)d_in[3];
    const float* Wk   = (const float*)d_in[4];
    const float* Wv   = (const float*)d_in[5];
    const float* Wo   = (const float*)d_in[6];
    float* out = (float*)d_out;

    __half *qhb, *khb, *vhb, *ohb, *xh, *wqh, *wkh, *wvh, *woh;
    cudaGetSymbolAddress((void**)&qhb, g_qh);
    cudaGetSymbolAddress((void**)&khb, g_kh);
    cudaGetSymbolAddress((void**)&vhb, g_vh);
    cudaGetSymbolAddress((void**)&ohb, g_oh);
    cudaGetSymbolAddress((void**)&xh, g_xh);
    cudaGetSymbolAddress((void**)&wqh, g_wqh);
    cudaGetSymbolAddress((void**)&wkh, g_wkh);
    cudaGetSymbolAddress((void**)&wvh, g_wvh);
    cudaGetSymbolAddress((void**)&woh, g_woh);

    // prep: x -> half; 4 weight transposes in one launch
    {
        int n8 = M_TOK * HIDDEN / 8;
        f2h_kernel<<<(n8 + 255) / 256, 256>>>(x, xh, n8);
        int c0 = 6400, c1 = c0 + 1600, c2 = c1 + 1600, ctot = c2 + 6400;
        dim3 blk(32, 8);
        f2h_transpose4_kernel<<<ctot, blk>>>(
            Wq, wqh, HIDDEN, NH * HD, c0,
            Wk, wkh, HIDDEN, NKV * HD, c1,
            Wv, wvh, HIDDEN, NKV * HD, c2,
            Wo, woh, NH * HD, HIDDEN);
    }

    cudaFuncSetAttribute(h16_gemm3_kernel<__half>,
                         cudaFuncAttributeMaxDynamicSharedMemorySize, GEMM_SMEM);
    cudaFuncSetAttribute(h16_gemm3_kernel<float>,
                         cudaFuncAttributeMaxDynamicSharedMemorySize, GEMM_SMEM);

    // fused Q/K/V projections (fp16 mma, half outputs)
    {
        dim3 g(30, M_TOK / 128);
        h16_gemm3_kernel<__half><<<g, 256, GEMM_SMEM>>>(
            xh,
            wqh, qhb, NH * HD, 20,
            wkh, khb, NKV * HD, 25,
            wvh, vhb, NKV * HD,
            M_TOK, HIDDEN);
    }

    // fused RoPE (half2)
    {
        int tq = M_TOK * NH * 20;
        int tk = M_TOK * NKV * 20;
        int tot = tq + tk;
        rope_fused_kernel<<<(tot + 255) / 256, 256>>>(qhb, khb, cosf, sinf, tq, tot);
    }

    // attention (fp16 mma flash, KT=128, double-buffered, trans-V)
    {
        cudaFuncSetAttribute(attn_h16_kernel,
                             cudaFuncAttributeMaxDynamicSharedMemorySize, ATT_SMEM3);
        dim3 ga(SEQ / 128, NH, BATCH);
        attn_h16_kernel<<<ga, 256, ATT_SMEM3>>>(qhb, khb, vhb, ohb);
    }

    // output projection (fp16 mma, fp32 output)
    {
        dim3 go(HIDDEN / 128, M_TOK / 128);
        h16_gemm3_kernel<float><<<go, 256, GEMM_SMEM>>>(
            ohb,
            woh, out, HIDDEN, 20,
            woh, out, HIDDEN, 20,
            woh, out, HIDDEN,
            M_TOK, HIDDEN);
    }
}

// round 15
// speedup vs baseline: 1.9656x; 1.0582x over previous
#include <cuda_runtime.h>
#include <cuda_fp16.h>
#include <math.h>
#include <stdint.h>

#define HIDDEN 2560
#define NH 32
#define NKV 8
#define HD 80
#define BATCH 2
#define SEQ 2048
#define M_TOK (BATCH * SEQ)   // 4096

// ---------------- scratch (static device globals; no runtime alloc) ----------
__device__ __half g_qh[M_TOK * NH * HD];
__device__ __half g_kh[M_TOK * NKV * HD];
__device__ __half g_vh[M_TOK * NKV * HD];
__device__ __half g_oh[M_TOK * NH * HD];       // attn out, half, K-major
__device__ __half g_xh[M_TOK * HIDDEN];        // x rounded to half
__device__ __half g_wqh[HIDDEN * NH * HD];     // weights: NATURAL [K,N] half
__device__ __half g_wkh[HIDDEN * NKV * HD];
__device__ __half g_wvh[HIDDEN * NKV * HD];
__device__ __half g_woh[NH * HD * HIDDEN];

__device__ __forceinline__ void mma_f16(float* c, const unsigned* a,
                                        unsigned b0, unsigned b1) {
    asm volatile(
        "mma.sync.aligned.m16n8k16.row.col.f32.f16.f16.f32 "
        "{%0,%1,%2,%3}, {%4,%5,%6,%7}, {%8,%9}, {%0,%1,%2,%3};"
        : "+f"(c[0]), "+f"(c[1]), "+f"(c[2]), "+f"(c[3])
        : "r"(a[0]), "r"(a[1]), "r"(a[2]), "r"(a[3]),
          "r"(b0), "r"(b1));
}

__device__ __forceinline__ void ldsm_x4(unsigned& r0, unsigned& r1,
                                        unsigned& r2, unsigned& r3,
                                        uint32_t addr) {
    asm volatile("ldmatrix.sync.aligned.m8n8.x4.shared.b16 {%0,%1,%2,%3}, [%4];"
                 : "=r"(r0), "=r"(r1), "=r"(r2), "=r"(r3) : "r"(addr));
}

__device__ __forceinline__ void ldsm_x4_t(unsigned& r0, unsigned& r1,
                                          unsigned& r2, unsigned& r3,
                                          uint32_t addr) {
    asm volatile("ldmatrix.sync.aligned.m8n8.x4.trans.shared.b16 {%0,%1,%2,%3}, [%4];"
                 : "=r"(r0), "=r"(r1), "=r"(r2), "=r"(r3) : "r"(addr));
}

__device__ __forceinline__ unsigned packh2(float x, float y) {
    __half2 h = __floats2half2_rn(x, y);
    return *(unsigned*)&h;
}

__device__ __forceinline__ void cp_async16(void* smem_ptr, const void* gptr) {
    unsigned saddr = (unsigned)__cvta_generic_to_shared(smem_ptr);
    asm volatile("cp.async.cg.shared.global [%0], [%1], 16;\n"
                 :: "r"(saddr), "l"(gptr));
}
__device__ __forceinline__ void cp_commit() {
    asm volatile("cp.async.commit_group;\n");
}
__device__ __forceinline__ void cp_wait0() {
    asm volatile("cp.async.wait_group 0;\n");
}
__device__ __forceinline__ void cp_wait1() {
    asm volatile("cp.async.wait_group 1;\n");
}

// typed paired store
__device__ __forceinline__ void store2(float* p, float a, float b) {
    *(float2*)p = make_float2(a, b);
}
__device__ __forceinline__ void store2(__half* p, float a, float b) {
    *(__half2*)p = __floats2half2_rn(a, b);
}

// ---------------- prep: fp32 -> fp16, 5 segments in one launch -----------------
__global__ void f2h5_kernel(
    const float* __restrict__ i0, __half* __restrict__ o0, int c0,
    const float* __restrict__ i1, __half* __restrict__ o1, int c1,
    const float* __restrict__ i2, __half* __restrict__ o2, int c2,
    const float* __restrict__ i3, __half* __restrict__ o3, int c3,
    const float* __restrict__ i4, __half* __restrict__ o4)
{
    int i = blockIdx.x * blockDim.x + threadIdx.x;
    const float* in; __half* out;
    if (i < c0)      { in = i0; out = o0; }
    else if (i < c1) { in = i1; out = o1; i -= c0; }
    else if (i < c2) { in = i2; out = o2; i -= c1; }
    else if (i < c3) { in = i3; out = o3; i -= c2; }
    else             { in = i4; out = o4; i -= c3; }

    const float4* ip = (const float4*)in + (size_t)i * 2;
    float4 a = ip[0], b = ip[1];
    uint4 o;
    o.x = packh2(a.x, a.y); o.y = packh2(a.z, a.w);
    o.z = packh2(b.x, b.y); o.w = packh2(b.z, b.w);
    *((uint4*)out + i) = o;
}

// ---------------- pipelined FP16 GEMM (BK=64, trans-B, 3-stage), 3 segments ----
// A: [M,K] rows padded 64->72 halves (144B; 36 words == 4 mod 32).
// B: NATURAL [K,N]; tile 64 x 128 halves, rows padded to 136 (272B; 68 == 4 mod 32).
// B fragments via ldmatrix.x4.trans (HW transpose).
#define ASTRH 72
#define BSTRH 136
#define ATILEH (128 * ASTRH)            // 9216 halves
#define BTILEH (64 * BSTRH)             // 8704 halves
#define STGH  (ATILEH + BTILEH)         // 17920 halves per stage
#define GEMM_SMEM (3 * STGH * 2)        // 107520 bytes

template <typename OutT>
__global__ __launch_bounds__(256) void h16_gemm3_kernel(
    const __half* __restrict__ A,
    const __half* __restrict__ B0, OutT* __restrict__ C0, int N0, int xs0,
    const __half* __restrict__ B1, OutT* __restrict__ C1, int N1, int xs1,
    const __half* __restrict__ B2, OutT* __restrict__ C2, int N2,
    int M, int K)
{
    extern __shared__ __half smh[];
    const uint32_t sbase = (uint32_t)__cvta_generic_to_shared(smh);

    const int bx = blockIdx.x;
    const __half* B; OutT* C; int N; int bxl;
    if (bx < xs0)      { B = B0; C = C0; N = N0; bxl = bx; }
    else if (bx < xs1) { B = B1; C = C1; N = N1; bxl = bx - xs0; }
    else               { B = B2; C = C2; N = N2; bxl = bx - xs1; }

    const int tid  = threadIdx.x;
    const int lane = tid & 31;
    const int warp = tid >> 5;
    const int wm   = (warp & 3) * 32;
    const int wn   = (warp >> 2) * 64;
    const int bm   = blockIdx.y * 128;
    const int bn   = bxl * 128;
    const int lq   = lane >> 2;
    const int lr   = lane & 3;

    const int arow_l = (lane & 7) + ((lane >> 3) & 1) * 8;
    const int awrd_l = (lane >> 4) * 4;
    // trans-ldmatrix lane map (rows = k, cols = n)
    const int trow_l = (lane & 7) + ((lane >> 3) & 1) * 8;
    const int tcol_l = (lane >> 4) * 8;

    const int acr = tid >> 3;           // A: 0..31 (+32*i), chunk tid&7
    const int acc_ = tid & 7;
    const int bcr = tid >> 4;           // B: 0..15 (+16*i), chunk tid&15
    const int bcc = tid & 15;

    float acc[2][8][4];
    #pragma unroll
    for (int i = 0; i < 2; i++)
        #pragma unroll
        for (int j = 0; j < 8; j++)
            #pragma unroll
            for (int r = 0; r < 4; r++) acc[i][j][r] = 0.f;

    const int T = K / 64;

    auto issue = [&](int t) {
        __half* sA = smh + (t % 3) * STGH;
        __half* sB = sA + ATILEH;
        const int k0 = t * 64;
        #pragma unroll
        for (int i = 0; i < 4; i++) {
            int r = acr + i * 32;
            cp_async16(sA + r * ASTRH + acc_ * 8,
                       A + (size_t)(bm + r) * K + k0 + acc_ * 8);
            int br = bcr + i * 16;
            cp_async16(sB + br * BSTRH + bcc * 8,
                       B + (size_t)(k0 + br) * N + bn + bcc * 8);
        }
    };

    issue(0); cp_commit();
    issue(1); cp_commit();

    for (int t = 0; t < T; t++) {
        cp_wait1();
        __syncthreads();

        if (t + 2 < T) issue(t + 2);
        cp_commit();

        const uint32_t stA = sbase + (uint32_t)((t % 3) * STGH) * 2;
        const uint32_t stB = stA + ATILEH * 2;
        #pragma unroll
        for (int ks = 0; ks < 4; ks++) {
            const int c8 = ks * 8;
            unsigned af[2][4];
            #pragma unroll
            for (int mi = 0; mi < 2; mi++)
                ldsm_x4(af[mi][0], af[mi][1], af[mi][2], af[mi][3],
                        stA + (uint32_t)(wm + mi * 16 + arow_l) * 144
                            + (uint32_t)(c8 + awrd_l) * 4);
            unsigned bf[8][2];
            #pragma unroll
            for (int nb = 0; nb < 8; nb += 2)
                ldsm_x4_t(bf[nb][0], bf[nb][1], bf[nb + 1][0], bf[nb + 1][1],
                          stB + (uint32_t)(ks * 16 + trow_l) * 272
                              + (uint32_t)(wn + nb * 8 + tcol_l) * 2);
            #pragma unroll
            for (int mi = 0; mi < 2; mi++)
                #pragma unroll
                for (int ni = 0; ni < 8; ni++)
                    mma_f16(acc[mi][ni], af[mi], bf[ni][0], bf[ni][1]);
        }
    }

    #pragma unroll
    for (int mi = 0; mi < 2; mi++) {
        int m = bm + wm + mi * 16 + lq;
        #pragma unroll
        for (int ni = 0; ni < 8; ni++) {
            int n = bn + wn + ni * 8 + lr * 2;
            store2(C + (size_t)m * N + n,       acc[mi][ni][0], acc[mi][ni][1]);
            store2(C + (size_t)(m + 8) * N + n, acc[mi][ni][2], acc[mi][ni][3]);
        }
    }
}

// ---------------- fused RoPE (half2 vectorized) ---------------------------------
__global__ void rope_fused_kernel(__half* __restrict__ qb, __half* __restrict__ kb,
                                  const float* __restrict__ cosf,
                                  const float* __restrict__ sinf,
                                  int tq, int total)
{
    int idx = blockIdx.x * blockDim.x + threadIdx.x;
    if (idx >= total) return;
    __half* t; int nheads; int li;
    if (idx < tq) { t = qb; nheads = NH;  li = idx; }
    else          { t = kb; nheads = NKV; li = idx - tq; }

    int i2  = li % 20;
    int h   = (li / 20) % nheads;
    int tok = li / (20 * nheads);
    int s   = tok % SEQ;
    int i   = i2 * 2;

    __half* p = t + (size_t)tok * nheads * HD + h * HD;
    float2 xa = __half22float2(*(__half2*)(p + i));
    float2 xb = __half22float2(*(__half2*)(p + i + 40));
    float2 c1 = *(const float2*)(cosf + s * HD + i);
    float2 s1 = *(const float2*)(sinf + s * HD + i);
    float2 c2 = *(const float2*)(cosf + s * HD + i + 40);
    float2 s2 = *(const float2*)(sinf + s * HD + i + 40);
    *(__half2*)(p + i)      = __floats2half2_rn(xa.x * c1.x - xb.x * s1.x,
                                                xa.y * c1.y - xb.y * s1.y);
    *(__half2*)(p + i + 40) = __floats2half2_rn(xb.x * c2.x + xa.x * s2.x,
                                                xb.y * c2.y + xa.y * s2.y);
}

// ---------------- FP16 flash attention: P in registers, no P smem --------------
#define QWD 44                 // Q/K/V row stride in words
#define KVW (128 * QWD)        // words per K or V buffer = 5632
#define ATT_WORDS4 (KVW + 2 * KVW + 2 * KVW)   // 28160 words
#define ATT_SMEM4  (ATT_WORDS4 * 4)            // 112640 bytes

__global__ __launch_bounds__(256) void attn_h16_kernel(
    const __half* __restrict__ q, const __half* __restrict__ k,
    const __half* __restrict__ v, __half* __restrict__ oh)
{
    extern __shared__ unsigned sw[];
    __half* Qh = (__half*)sw;
    const uint32_t sbase = (uint32_t)__cvta_generic_to_shared(sw);
    const uint32_t Qb = sbase;
    const uint32_t Kb0 = sbase + KVW * 4;
    const uint32_t Vb0 = sbase + 3 * KVW * 4;

    const int b    = blockIdx.z;
    const int h    = blockIdx.y;
    const int qt   = gridDim.x - 1 - blockIdx.x;
    const int kvh  = h >> 2;
    const int tid  = threadIdx.x;
    const int lane = tid & 31;
    const int warp = tid >> 5;
    const int lq   = lane >> 2;
    const int lr   = lane & 3;
    const int wr   = warp * 16;
    const float scale = rsqrtf((float)HD);

    const int arow_l = (lane & 7) + ((lane >> 3) & 1) * 8;
    const int awrd_l = (lane >> 4) * 4;
    const int brow_l = (lane & 7) + (lane >> 4) * 8;
    const int bwrd_l = ((lane >> 3) & 1) * 4;
    const int vrow_l = (lane & 7) + ((lane >> 3) & 1) * 8;
    const int vcol_l = (lane >> 4) * 8;

    // ---- Q load ----
    {
        const __half* qsrc = q + ((size_t)(b * SEQ + qt * 128)) * (NH * HD) + h * HD;
        #pragma unroll
        for (int i = 0; i < 5; i++) {
            int f = tid + i * 256;
            int row = f / 10, ch = f % 10;
            cp_async16(Qh + row * (2 * QWD) + ch * 8,
                       qsrc + (size_t)row * (NH * HD) + ch * 8);
        }
        cp_commit();
    }

    auto issue_kv = [&](int kt) {
        __half* Kh = (__half*)(sw + KVW + (kt & 1) * KVW);
        __half* Vh = (__half*)(sw + 3 * KVW + (kt & 1) * KVW);
        const __half* ksrc = k + ((size_t)(b * SEQ + kt * 128)) * (NKV * HD) + kvh * HD;
        const __half* vsrc = v + ((size_t)(b * SEQ + kt * 128)) * (NKV * HD) + kvh * HD;
        #pragma unroll
        for (int i = 0; i < 5; i++) {
            int f = tid + i * 256;
            int row = f / 10, ch = f % 10;
            cp_async16(Kh + row * (2 * QWD) + ch * 8,
                       ksrc + (size_t)row * (NKV * HD) + ch * 8);
            cp_async16(Vh + row * (2 * QWD) + ch * 8,
                       vsrc + (size_t)row * (NKV * HD) + ch * 8);
        }
    };

    issue_kv(0); cp_commit();

    float oacc[10][4];
    #pragma unroll
    for (int i = 0; i < 10; i++)
        #pragma unroll
        for (int j = 0; j < 4; j++) oacc[i][j] = 0.f;
    float m0 = -INFINITY, m1 = -INFINITY;
    float l0 = 0.f, l1 = 0.f;

    const int row0 = qt * 128 + wr + lq;
    const int row1 = row0 + 8;

    for (int kt = 0; kt <= qt; kt++) {
        if (kt + 1 <= qt) issue_kv(kt + 1);
        cp_commit();
        if (kt + 1 <= qt) cp_wait1(); else cp_wait0();
        __syncthreads();

        const uint32_t Kb = Kb0 + (uint32_t)(kt & 1) * (KVW * 4);
        const uint32_t Vb = Vb0 + (uint32_t)(kt & 1) * (KVW * 4);

        // ---- QK^T ----
        float sc[16][4];
        #pragma unroll
        for (int ni = 0; ni < 16; ni++)
            #pragma unroll
            for (int j = 0; j < 4; j++) sc[ni][j] = 0.f;

        #pragma unroll
        for (int ks = 0; ks < 5; ks++) {
            const int c8 = ks * 8;
            unsigned af[4];
            ldsm_x4(af[0], af[1], af[2], af[3],
                    Qb + (uint32_t)(wr + arow_l) * 176 + (uint32_t)(c8 + awrd_l) * 4);
            unsigned bf[16][2];
            #pragma unroll
            for (int nb = 0; nb < 16; nb += 2)
                ldsm_x4(bf[nb][0], bf[nb][1], bf[nb + 1][0], bf[nb + 1][1],
                        Kb + (uint32_t)(nb * 8 + brow_l) * 176
                           + (uint32_t)(c8 + bwrd_l) * 4);
            #pragma unroll
            for (int ni = 0; ni < 16; ni++)
                mma_f16(sc[ni], af, bf[ni][0], bf[ni][1]);
        }

        // ---- scale + causal mask ----
        const bool diag = (kt == qt);
        #pragma unroll
        for (int ni = 0; ni < 16; ni++) {
            int c = kt * 128 + ni * 8 + lr * 2;
            sc[ni][0] = (diag && c     > row0) ? -1e30f : sc[ni][0] * scale;
            sc[ni][1] = (diag && c + 1 > row0) ? -1e30f : sc[ni][1] * scale;
            sc[ni][2] = (diag && c     > row1) ? -1e30f : sc[ni][2] * scale;
            sc[ni][3] = (diag && c + 1 > row1) ? -1e30f : sc[ni][3] * scale;
        }

        // ---- online softmax ----
        float rm0 = -1e30f, rm1 = -1e30f;
        #pragma unroll
        for (int ni = 0; ni < 16; ni++) {
            rm0 = fmaxf(rm0, fmaxf(sc[ni][0], sc[ni][1]));
            rm1 = fmaxf(rm1, fmaxf(sc[ni][2], sc[ni][3]));
        }
        rm0 = fmaxf(rm0, __shfl_xor_sync(0xffffffffu, rm0, 1));
        rm0 = fmaxf(rm0, __shfl_xor_sync(0xffffffffu, rm0, 2));
        rm1 = fmaxf(rm1, __shfl_xor_sync(0xffffffffu, rm1, 1));
        rm1 = fmaxf(rm1, __shfl_xor_sync(0xffffffffu, rm1, 2));

        float m0n = fmaxf(m0, rm0);
        float m1n = fmaxf(m1, rm1);
        float a0  = __expf(m0 - m0n);
        float a1  = __expf(m1 - m1n);
        m0 = m0n; m1 = m1n;

        // ---- exp + pack P directly into A-fragment registers ----
        unsigned pf[16][2];
        float rs0 = 0.f, rs1 = 0.f;
        #pragma unroll
        for (int ni = 0; ni < 16; ni++) {
            float p0 = __expf(sc[ni][0] - m0n);
            float p1 = __expf(sc[ni][1] - m0n);
            float p2 = __expf(sc[ni][2] - m1n);
            float p3 = __expf(sc[ni][3] - m1n);
            rs0 += p0 + p1;
            rs1 += p2 + p3;
            pf[ni][0] = packh2(p0, p1);
            pf[ni][1] = packh2(p2, p3);
        }
        rs0 += __shfl_xor_sync(0xffffffffu, rs0, 1);
        rs0 += __shfl_xor_sync(0xffffffffu, rs0, 2);
        rs1 += __shfl_xor_sync(0xffffffffu, rs1, 1);
        rs1 += __shfl_xor_sync(0xffffffffu, rs1, 2);
        l0 = l0 * a0 + rs0;
        l1 = l1 * a1 + rs1;

        #pragma unroll
        for (int ni = 0; ni < 10; ni++) {
            oacc[ni][0] *= a0; oacc[ni][1] *= a0;
            oacc[ni][2] *= a1; oacc[ni][3] *= a1;
        }

        // ---- PV: P from registers, V via ldmatrix.trans ----
        #pragma unroll
        for (int ks = 0; ks < 8; ks++) {
            unsigned af[4];
            af[0] = pf[2 * ks    ][0];
            af[1] = pf[2 * ks    ][1];
            af[2] = pf[2 * ks + 1][0];
            af[3] = pf[2 * ks + 1][1];
            unsigned bf[10][2];
            #pragma unroll
            for (int nb = 0; nb < 10; nb += 2)
                ldsm_x4_t(bf[nb][0], bf[nb][1], bf[nb + 1][0], bf[nb + 1][1],
                          Vb + (uint32_t)(ks * 16 + vrow_l) * 176
                             + (uint32_t)(nb * 8 + vcol_l) * 2);
            #pragma unroll
            for (int ni = 0; ni < 10; ni++)
                mma_f16(oacc[ni], af, bf[ni][0], bf[ni][1]);
        }
        __syncthreads();   // protect buf (kt&1) before re-issue at kt+2
    }

    // ---- epilogue ----
    const float inv0 = 1.0f / l0;
    const float inv1 = 1.0f / l1;
    #pragma unroll
    for (int ni = 0; ni < 10; ni++) {
        int c = ni * 8 + lr * 2;
        __half2* p0 = (__half2*)(oh + (size_t)(b * SEQ + row0) * (NH * HD) + h * HD + c);
        __half2* p1 = (__half2*)(oh + (size_t)(b * SEQ + row1) * (NH * HD) + h * HD + c);
        *p0 = __floats2half2_rn(oacc[ni][0] * inv0, oacc[ni][1] * inv0);
        *p1 = __floats2half2_rn(oacc[ni][2] * inv1, oacc[ni][3] * inv1);
    }
}

// ---------------- launch --------------------------------------------------------
extern "C" void kernel_launch(void* const* d_in, const int* in_sizes, int n_in,
                              void* d_out, int out_size)
{
    const float* x    = (const float*)d_in[0];
    const float* cosf = (const float*)d_in[1];
    const float* sinf = (const float*)d_in[2];
    const float* Wq   = (const float*)d_in[3];
    const float* Wk   = (const float*)d_in[4];
    const float* Wv   = (const float*)d_in[5];
    const float* Wo   = (const float*)d_in[6];
    float* out = (float*)d_out;

    __half *qhb, *khb, *vhb, *ohb, *xh, *wqh, *wkh, *wvh, *woh;
    cudaGetSymbolAddress((void**)&qhb, g_qh);
    cudaGetSymbolAddress((void**)&khb, g_kh);
    cudaGetSymbolAddress((void**)&vhb, g_vh);
    cudaGetSymbolAddress((void**)&ohb, g_oh);
    cudaGetSymbolAddress((void**)&xh, g_xh);
    cudaGetSymbolAddress((void**)&wqh, g_wqh);
    cudaGetSymbolAddress((void**)&wkh, g_wkh);
    cudaGetSymbolAddress((void**)&wvh, g_wvh);
    cudaGetSymbolAddress((void**)&woh, g_woh);

    // prep: all fp32 -> fp16 conversions in one launch (weights stay [K,N])
    {
        int n_x  = M_TOK * HIDDEN / 8;            // 1310720
        int n_wq = HIDDEN * NH * HD / 8;          // 819200
        int n_wk = HIDDEN * NKV * HD / 8;         // 204800
        int c0 = n_x, c1 = c0 + n_wq, c2 = c1 + n_wk, c3 = c2 + n_wk;
        int ctot = c3 + n_wq;
        f2h5_kernel<<<(ctot + 255) / 256, 256>>>(
            x, xh, c0,
            Wq, wqh, c1,
            Wk, wkh, c2,
            Wv, wvh, c3,
            Wo, woh);
    }

    cudaFuncSetAttribute(h16_gemm3_kernel<__half>,
                         cudaFuncAttributeMaxDynamicSharedMemorySize, GEMM_SMEM);
    cudaFuncSetAttribute(h16_gemm3_kernel<float>,
                         cudaFuncAttributeMaxDynamicSharedMemorySize, GEMM_SMEM);

    // fused Q/K/V projections (fp16 mma, half outputs)
    {
        dim3 g(30, M_TOK / 128);
        h16_gemm3_kernel<__half><<<g, 256, GEMM_SMEM>>>(
            xh,
            wqh, qhb, NH * HD, 20,
            wkh, khb, NKV * HD, 25,
            wvh, vhb, NKV * HD,
            M_TOK, HIDDEN);
    }

    // fused RoPE (half2)
    {
        int tq = M_TOK * NH * 20;
        int tk = M_TOK * NKV * 20;
        int tot = tq + tk;
        rope_fused_kernel<<<(tot + 255) / 256, 256>>>(qhb, khb, cosf, sinf, tq, tot);
    }

    // attention (fp16 mma flash, P-in-registers)
    {
        cudaFuncSetAttribute(attn_h16_kernel,
                             cudaFuncAttributeMaxDynamicSharedMemorySize, ATT_SMEM4);
        dim3 ga(SEQ / 128, NH, BATCH);
        attn_h16_kernel<<<ga, 256, ATT_SMEM4>>>(qhb, khb, vhb, ohb);
    }

    // output projection (fp16 mma, fp32 output)
    {
        dim3 go(HIDDEN / 128, M_TOK / 128);
        h16_gemm3_kernel<float><<<go, 256, GEMM_SMEM>>>(
            ohb,
            woh, out, HIDDEN, 20,
            woh, out, HIDDEN, 20,
            woh, out, HIDDEN,
            M_TOK, HIDDEN);
    }
}